// round 2
// baseline (speedup 1.0000x reference)
#include <cuda_runtime.h>
#include <math.h>

#define D   1024
#define H1  4096
#define H2  4096

// ---------------- scratch (static device globals; no allocation) ----------------
__device__ float  g_sW1[(size_t)H1 * D];   // s[h] * W1[h,i]  (16 MB)
__device__ float  g_u0[H1];                // tanh(a0)
__device__ float  g_g[H1];                 // -2*u0*s*||W1[h,:]||^2
__device__ float  g_coefQ[H2];             // -2*W3[j]*v0[j]*t[j]
__device__ double g_acc;                   // global scalar accumulator

// ---------------- init ----------------
__global__ void k_init() { g_acc = 0.0; }

// ---------------- K1: layer-1 fused row pass ----------------
// Per h: a0 = W1[h,:].x + b1[h]; r = ||W1[h,:]||^2;
//        u0 = tanh(a0); s = 1-u0^2; g = -2*u0*s*r; write s*W1 row.
__global__ __launch_bounds__(256) void k_layer1(const float* __restrict__ W1,
                                                const float* __restrict__ x,
                                                const float* __restrict__ b1) {
    int h = blockIdx.x;
    int t = threadIdx.x;  // 256 threads, D/4 = 256 float4 per row
    const float4* W4 = reinterpret_cast<const float4*>(W1 + (size_t)h * D);
    const float4* x4 = reinterpret_cast<const float4*>(x);
    float4 w  = W4[t];
    float4 xv = x4[t];
    float dot = w.x * xv.x + w.y * xv.y + w.z * xv.z + w.w * xv.w;
    float r   = w.x * w.x  + w.y * w.y  + w.z * w.z  + w.w * w.w;

    __shared__ float sd[256], sr[256];
    sd[t] = dot; sr[t] = r;
    __syncthreads();
    #pragma unroll
    for (int o = 128; o > 0; o >>= 1) {
        if (t < o) { sd[t] += sd[t + o]; sr[t] += sr[t + o]; }
        __syncthreads();
    }
    __shared__ float s_sh;
    if (t == 0) {
        float a0 = sd[0] + b1[h];
        float u0 = tanhf(a0);
        float s  = 1.0f - u0 * u0;
        s_sh     = s;
        g_u0[h]  = u0;
        g_g[h]   = -2.0f * u0 * s * sr[0];
    }
    __syncthreads();
    float s = s_sh;
    float4 o4 = make_float4(w.x * s, w.y * s, w.z * s, w.w * s);
    reinterpret_cast<float4*>(g_sW1 + (size_t)h * D)[t] = o4;
}

// ---------------- K2: layer-2 fused row pass ----------------
// Per j: z0 = W2[j,:].u0 + b2[j]; sz2 = W2[j,:].g;
//        v0 = tanh(z0); t = 1-v0^2;
//        acc += W3[j]*t*sz2;  coefQ[j] = -2*W3[j]*v0*t.
__global__ __launch_bounds__(256) void k_layer2(const float* __restrict__ W2,
                                                const float* __restrict__ b2,
                                                const float* __restrict__ W3) {
    int j = blockIdx.x;
    int t = threadIdx.x;  // 256 threads, H1/4 = 1024 float4 per row
    const float4* W4 = reinterpret_cast<const float4*>(W2 + (size_t)j * H1);
    const float4* u4 = reinterpret_cast<const float4*>(g_u0);
    const float4* g4 = reinterpret_cast<const float4*>(g_g);
    float z0 = 0.f, sz2 = 0.f;
    #pragma unroll
    for (int k = 0; k < 4; k++) {
        int idx = t + k * 256;
        float4 w  = W4[idx];
        float4 u  = u4[idx];
        float4 gg = g4[idx];
        z0  += w.x * u.x  + w.y * u.y  + w.z * u.z  + w.w * u.w;
        sz2 += w.x * gg.x + w.y * gg.y + w.z * gg.z + w.w * gg.w;
    }
    __shared__ float sd[256], sr[256];
    sd[t] = z0; sr[t] = sz2;
    __syncthreads();
    #pragma unroll
    for (int o = 128; o > 0; o >>= 1) {
        if (t < o) { sd[t] += sd[t + o]; sr[t] += sr[t + o]; }
        __syncthreads();
    }
    if (t == 0) {
        float v0 = tanhf(sd[0] + b2[j]);
        float tt = 1.0f - v0 * v0;
        float w3 = W3[j];
        atomicAdd(&g_acc, (double)(w3 * tt * sr[0]));
        g_coefQ[j] = -2.0f * w3 * v0 * tt;
    }
}

// ---------------- K3: main GEMM + fused square/reduce epilogue ----------------
// z1[i,j] = sum_h (s[h]*W1[h,i]) * W2[j,h]
// contribution += coefQ[j] * z1[i,j]^2   (z1 never hits DRAM)
#define BI 128
#define BJ 128
#define BK 8

__global__ __launch_bounds__(256) void k_gemm(const float* __restrict__ W2) {
    __shared__ float As[BK][BI];       // As[hh][i]
    __shared__ float Bs[BK][BJ + 4];   // Bs[hh][j], padded (132 % 4 == 0, fp4-aligned rows)

    const int bi0 = blockIdx.x * BI;
    const int bj0 = blockIdx.y * BJ;
    const int t   = threadIdx.x;       // 256
    const int tx  = t & 15;            // i micro-tile index (16)
    const int ty  = t >> 4;            // j micro-tile index (16)

    // global-load assignments
    const int a_hh = t >> 5;           // 0..7
    const int a_i  = (t & 31) * 4;     // 0..124
    const int b_jj = t >> 1;           // 0..127
    const int b_h  = (t & 1) * 4;      // 0 or 4

    float acc[8][8];
    #pragma unroll
    for (int l = 0; l < 8; l++)
        #pragma unroll
        for (int k = 0; k < 8; k++) acc[l][k] = 0.f;

    for (int h0 = 0; h0 < H1; h0 += BK) {
        float4 av = *reinterpret_cast<const float4*>(
            &g_sW1[(size_t)(h0 + a_hh) * D + bi0 + a_i]);
        float4 bv = *reinterpret_cast<const float4*>(
            &W2[(size_t)(bj0 + b_jj) * H1 + h0 + b_h]);
        __syncthreads();
        *reinterpret_cast<float4*>(&As[a_hh][a_i]) = av;
        Bs[b_h + 0][b_jj] = bv.x;
        Bs[b_h + 1][b_jj] = bv.y;
        Bs[b_h + 2][b_jj] = bv.z;
        Bs[b_h + 3][b_jj] = bv.w;
        __syncthreads();
        #pragma unroll
        for (int hh = 0; hh < BK; hh++) {
            float a[8], b[8];
            *reinterpret_cast<float4*>(&a[0]) = *reinterpret_cast<float4*>(&As[hh][tx * 8]);
            *reinterpret_cast<float4*>(&a[4]) = *reinterpret_cast<float4*>(&As[hh][tx * 8 + 4]);
            *reinterpret_cast<float4*>(&b[0]) = *reinterpret_cast<float4*>(&Bs[hh][ty * 8]);
            *reinterpret_cast<float4*>(&b[4]) = *reinterpret_cast<float4*>(&Bs[hh][ty * 8 + 4]);
            #pragma unroll
            for (int l = 0; l < 8; l++)
                #pragma unroll
                for (int k = 0; k < 8; k++)
                    acc[l][k] = fmaf(b[l], a[k], acc[l][k]);
        }
    }

    // epilogue: sum_j coefQ[j] * sum_i z1^2 over this block's tile
    float part = 0.f;
    #pragma unroll
    for (int l = 0; l < 8; l++) {
        float c  = g_coefQ[bj0 + ty * 8 + l];
        float ss = 0.f;
        #pragma unroll
        for (int k = 0; k < 8; k++) ss = fmaf(acc[l][k], acc[l][k], ss);
        part = fmaf(c, ss, part);
    }
    __shared__ float red[256];
    red[t] = part;
    __syncthreads();
    #pragma unroll
    for (int o = 128; o > 0; o >>= 1) {
        if (t < o) red[t] += red[t + o];
        __syncthreads();
    }
    if (t == 0) atomicAdd(&g_acc, (double)red[0]);
}

// ---------------- finalize ----------------
__global__ void k_final(float* __restrict__ out) { out[0] = (float)g_acc; }

// ---------------- launch ----------------
extern "C" void kernel_launch(void* const* d_in, const int* in_sizes, int n_in,
                              void* d_out, int out_size) {
    const float* x  = (const float*)d_in[0];
    const float* W1 = (const float*)d_in[1];
    const float* b1 = (const float*)d_in[2];
    const float* W2 = (const float*)d_in[3];
    const float* b2 = (const float*)d_in[4];
    const float* W3 = (const float*)d_in[5];
    // d_in[6] = b3: unused (Laplacian of affine shift is zero)
    float* out = (float*)d_out;

    k_init<<<1, 1>>>();
    k_layer1<<<H1, 256>>>(W1, x, b1);
    k_layer2<<<H2, 256>>>(W2, b2, W3);
    dim3 grid(D / BI, H2 / BJ);
    k_gemm<<<grid, 256>>>(W2);
    k_final<<<1, 1>>>(out);
}

// round 4
// speedup vs baseline: 2.4759x; 2.4759x over previous
#include <cuda_runtime.h>
#include <cuda_bf16.h>
#include <math.h>
#include <stdint.h>

#define D   1024
#define H1  4096
#define H2  4096

// ---------------- scratch (static device globals; no allocation) ----------------
__device__ float          g_sW1[(size_t)H1 * D];     // s[h] * W1[h,i]  fp32 (16 MB)
__device__ float          g_u0[H1];
__device__ float          g_g[H1];
__device__ float          g_coefQ[H2];
__device__ double         g_acc;
__device__ __nv_bfloat16  g_W2hi[(size_t)H2 * H1];   // W2 split (32 MB)
__device__ __nv_bfloat16  g_W2lo[(size_t)H2 * H1];   // 32 MB
__device__ __nv_bfloat16  g_Ahi[(size_t)D * H1];     // (s*W1)^T split, [i][h] (8 MB)
__device__ __nv_bfloat16  g_Alo[(size_t)D * H1];     // 8 MB

// ---------------- portable PTX helpers (sm_80+: legal on plain sm_103 target) ----
__device__ __forceinline__ uint32_t smem_u32(const void* p) {
    uint32_t a;
    asm("{ .reg .u64 t; cvta.to.shared.u64 t, %1; cvt.u32.u64 %0, t; }" : "=r"(a) : "l"(p));
    return a;
}
__device__ __forceinline__ void cp16(uint32_t dst, const void* src) {
    asm volatile("cp.async.cg.shared.global [%0], [%1], 16;" :: "r"(dst), "l"(src));
}
#define CP_COMMIT() asm volatile("cp.async.commit_group;" ::: "memory")
template <int N>
__device__ __forceinline__ void cp_wait() {
    asm volatile("cp.async.wait_group %0;" :: "n"(N) : "memory");
}
__device__ __forceinline__ void ldm4(uint32_t addr, uint32_t r[4]) {
    asm volatile("ldmatrix.sync.aligned.m8n8.x4.shared.b16 {%0,%1,%2,%3}, [%4];"
                 : "=r"(r[0]), "=r"(r[1]), "=r"(r[2]), "=r"(r[3]) : "r"(addr));
}
__device__ __forceinline__ void mma16816(float c[4], const uint32_t a[4],
                                         uint32_t b0, uint32_t b1) {
    asm volatile("mma.sync.aligned.m16n8k16.row.col.f32.bf16.bf16.f32 "
                 "{%0,%1,%2,%3}, {%4,%5,%6,%7}, {%8,%9}, {%0,%1,%2,%3};"
                 : "+f"(c[0]), "+f"(c[1]), "+f"(c[2]), "+f"(c[3])
                 : "r"(a[0]), "r"(a[1]), "r"(a[2]), "r"(a[3]), "r"(b0), "r"(b1));
}
__device__ __forceinline__ uint32_t pack2bf(float a, float b) {
    unsigned short ua = __bfloat16_as_ushort(__float2bfloat16_rn(a));
    unsigned short ub = __bfloat16_as_ushort(__float2bfloat16_rn(b));
    return (uint32_t)ua | ((uint32_t)ub << 16);
}

// ---------------- init ----------------
__global__ void k_init() { g_acc = 0.0; }

// ---------------- K1: layer-1 fused row pass (fp32) ----------------
__global__ __launch_bounds__(256) void k_layer1(const float* __restrict__ W1,
                                                const float* __restrict__ x,
                                                const float* __restrict__ b1) {
    int h = blockIdx.x;
    int t = threadIdx.x;
    const float4* W4 = reinterpret_cast<const float4*>(W1 + (size_t)h * D);
    const float4* x4 = reinterpret_cast<const float4*>(x);
    float4 w  = W4[t];
    float4 xv = x4[t];
    float dot = w.x * xv.x + w.y * xv.y + w.z * xv.z + w.w * xv.w;
    float r   = w.x * w.x  + w.y * w.y  + w.z * w.z  + w.w * w.w;

    __shared__ float sd[256], sr[256];
    sd[t] = dot; sr[t] = r;
    __syncthreads();
    #pragma unroll
    for (int o = 128; o > 0; o >>= 1) {
        if (t < o) { sd[t] += sd[t + o]; sr[t] += sr[t + o]; }
        __syncthreads();
    }
    __shared__ float s_sh;
    if (t == 0) {
        float a0 = sd[0] + b1[h];
        float u0 = tanhf(a0);
        float s  = 1.0f - u0 * u0;
        s_sh     = s;
        g_u0[h]  = u0;
        g_g[h]   = -2.0f * u0 * s * sr[0];
    }
    __syncthreads();
    float s = s_sh;
    reinterpret_cast<float4*>(g_sW1 + (size_t)h * D)[t] =
        make_float4(w.x * s, w.y * s, w.z * s, w.w * s);
}

// ---------------- K_T: transpose + bf16-split s*W1 -> A_t[i][h] ----------------
__global__ __launch_bounds__(256) void k_transpose() {
    __shared__ float tile[32][33];
    int i0 = blockIdx.x * 32;
    int h0 = blockIdx.y * 32;
    int tx = threadIdx.x & 31;
    int ty = threadIdx.x >> 5;
    #pragma unroll
    for (int r = 0; r < 4; r++)
        tile[ty + r * 8][tx] = g_sW1[(size_t)(h0 + ty + r * 8) * D + i0 + tx];
    __syncthreads();
    #pragma unroll
    for (int r = 0; r < 4; r++) {
        int ii = ty + r * 8;
        float v = tile[tx][ii];
        __nv_bfloat16 hi = __float2bfloat16_rn(v);
        float lo = v - __bfloat162float(hi);
        size_t off = (size_t)(i0 + ii) * H1 + h0 + tx;
        g_Ahi[off] = hi;
        g_Alo[off] = __float2bfloat16_rn(lo);
    }
}

// ---------------- K2: layer-2 fused row pass + W2 bf16 split ----------------
__global__ __launch_bounds__(256) void k_layer2(const float* __restrict__ W2,
                                                const float* __restrict__ b2,
                                                const float* __restrict__ W3) {
    int j = blockIdx.x;
    int t = threadIdx.x;
    const float4* W4 = reinterpret_cast<const float4*>(W2 + (size_t)j * H1);
    const float4* u4 = reinterpret_cast<const float4*>(g_u0);
    const float4* g4 = reinterpret_cast<const float4*>(g_g);
    float z0 = 0.f, sz2 = 0.f;
    #pragma unroll
    for (int k = 0; k < 4; k++) {
        int idx = t + k * 256;
        float4 w  = W4[idx];
        float4 u  = u4[idx];
        float4 gg = g4[idx];
        z0  += w.x * u.x  + w.y * u.y  + w.z * u.z  + w.w * u.w;
        sz2 += w.x * gg.x + w.y * gg.y + w.z * gg.z + w.w * gg.w;
        __nv_bfloat16 hx = __float2bfloat16_rn(w.x), hy = __float2bfloat16_rn(w.y);
        __nv_bfloat16 hz = __float2bfloat16_rn(w.z), hw = __float2bfloat16_rn(w.w);
        uint2 hv, lv;
        hv.x = (uint32_t)__bfloat16_as_ushort(hx) | ((uint32_t)__bfloat16_as_ushort(hy) << 16);
        hv.y = (uint32_t)__bfloat16_as_ushort(hz) | ((uint32_t)__bfloat16_as_ushort(hw) << 16);
        lv.x = pack2bf(w.x - __bfloat162float(hx), w.y - __bfloat162float(hy));
        lv.y = pack2bf(w.z - __bfloat162float(hz), w.w - __bfloat162float(hw));
        size_t off = (size_t)j * H1 + (size_t)idx * 4;
        *reinterpret_cast<uint2*>(&g_W2hi[off]) = hv;
        *reinterpret_cast<uint2*>(&g_W2lo[off]) = lv;
    }
    __shared__ float sd[256], sr[256];
    sd[t] = z0; sr[t] = sz2;
    __syncthreads();
    #pragma unroll
    for (int o = 128; o > 0; o >>= 1) {
        if (t < o) { sd[t] += sd[t + o]; sr[t] += sr[t + o]; }
        __syncthreads();
    }
    if (t == 0) {
        float v0 = tanhf(sd[0] + b2[j]);
        float tt = 1.0f - v0 * v0;
        float w3 = W3[j];
        atomicAdd(&g_acc, (double)(w3 * tt * sr[0]));
        g_coefQ[j] = -2.0f * w3 * v0 * tt;
    }
}

// ---------------- K3: mma.sync split-bf16 GEMM + fused square/reduce ----------------
// z1[j,i] = sum_h W2[j,h]*(s*W1)^T[i,h];  acc += coefQ[j]*z1^2.
// Block 128(j) x 128(i) x K32; 8 warps (warp tile 32x64); cp.async double buffer.
// SMEM rows: 128B = [hi k0..31 | lo k0..31], chunk swizzle c^(row&7).
#define BK       32
#define NCH      (H1 / BK)           // 128
#define TILE_BY  16384               // 128 rows * 128B
#define STAGE_BY (2 * TILE_BY)       // A + B
#define GEMM_SMEM (1024 + 2 * STAGE_BY)

__global__ __launch_bounds__(256, 2) void k_gemm() {
    extern __shared__ char dyn[];
    uint32_t raw  = smem_u32(dyn);
    uint32_t base = (raw + 1023u) & ~1023u;
    char*    gen  = dyn + (base - raw);

    const int t    = threadIdx.x;
    const int w    = t >> 5;
    const int lane = t & 31;
    const int j0   = blockIdx.x * 128;
    const int i0   = blockIdx.y * 128;

    // -------- cp.async source pointers (4 A-chunks + 4 B-chunks per thread) ----
    // chunk id = q*256 + t; row = id>>3; c = id&7; c<4 -> hi, else lo.
    const char* srcA[4];
    const char* srcB[4];
    uint32_t    dstA[4], dstB[4];
    #pragma unroll
    for (int q = 0; q < 4; q++) {
        int id  = q * 256 + t;
        int row = id >> 3;
        int c   = id & 7;
        size_t goff = ((size_t)row) * H1 + (size_t)(c & 3) * 8;  // bf16 elements
        srcA[q] = (const char*)((c < 4 ? g_W2hi : g_W2lo) + (size_t)j0 * H1 + goff);
        srcB[q] = (const char*)((c < 4 ? g_Ahi  : g_Alo ) + (size_t)i0 * H1 + goff);
        uint32_t so = (uint32_t)(row * 128 + ((c ^ (row & 7)) << 4));
        dstA[q] = base + so;             // A tile at stage offset 0
        dstB[q] = base + TILE_BY + so;   // B tile at stage offset 16K
    }

    auto load_stage = [&](int s, int kc) {
        uint32_t sb = (uint32_t)s * STAGE_BY;
        const size_t gb = (size_t)kc * BK * 2;   // byte advance along k
        #pragma unroll
        for (int q = 0; q < 4; q++) cp16(dstA[q] + sb, srcA[q] + gb);
        #pragma unroll
        for (int q = 0; q < 4; q++) cp16(dstB[q] + sb, srcB[q] + gb);
        CP_COMMIT();
    };

    // -------- warp tiling: wm = w>>1 (m0 = 32*wm), wn = w&1 (n0 = 64*wn) ------
    const int m0 = (w >> 1) * 32;
    const int n0 = (w & 1) * 64;
    const uint32_t sw = (uint32_t)(lane & 7);           // row&7 == lane&7
    const uint32_t rsel = (uint32_t)(lane >> 4);        // 0/1: chunk pair half
    // ldmatrix row bases (byte addr without chunk term)
    uint32_t aRow[2], bRow[4];
    #pragma unroll
    for (int mt = 0; mt < 2; mt++)
        aRow[mt] = base + (uint32_t)((m0 + 16 * mt + (lane & 15)) * 128);
    #pragma unroll
    for (int bt = 0; bt < 4; bt++)
        bRow[bt] = base + TILE_BY + (uint32_t)((n0 + 16 * bt + (lane & 15)) * 128);

    float acc[2][8][4];
    #pragma unroll
    for (int mt = 0; mt < 2; mt++)
        #pragma unroll
        for (int nt = 0; nt < 8; nt++)
            #pragma unroll
            for (int e = 0; e < 4; e++) acc[mt][nt][e] = 0.f;

    load_stage(0, 0);

    #pragma unroll 1
    for (int k = 0; k < NCH; k++) {
        if (k + 1 < NCH) { load_stage((k + 1) & 1, k + 1); cp_wait<1>(); }
        else             { cp_wait<0>(); }
        __syncthreads();

        const uint32_t sb = (uint32_t)(k & 1) * STAGE_BY;
        #pragma unroll
        for (int ks = 0; ks < 2; ks++) {
            const uint32_t chi = (uint32_t)(ks * 2) + rsel;       // hi chunks 0..3
            const uint32_t clo = chi + 4;                          // lo chunks 4..7
            uint32_t ah[2][4], al[2][4];
            #pragma unroll
            for (int mt = 0; mt < 2; mt++) {
                ldm4(aRow[mt] + sb + ((chi ^ sw) << 4), ah[mt]);
                ldm4(aRow[mt] + sb + ((clo ^ sw) << 4), al[mt]);
            }
            #pragma unroll
            for (int bt = 0; bt < 4; bt++) {
                uint32_t bh[4], bl[4];
                ldm4(bRow[bt] + sb + ((chi ^ sw) << 4), bh);
                ldm4(bRow[bt] + sb + ((clo ^ sw) << 4), bl);
                #pragma unroll
                for (int mt = 0; mt < 2; mt++) {
                    #pragma unroll
                    for (int p = 0; p < 2; p++) {
                        float* cc = acc[mt][bt * 2 + p];
                        mma16816(cc, ah[mt], bh[p], bh[2 + p]);   // hi*hi
                        mma16816(cc, ah[mt], bl[p], bl[2 + p]);   // hi*lo
                        mma16816(cc, al[mt], bh[p], bh[2 + p]);   // lo*hi
                    }
                }
            }
        }
        __syncthreads();
    }

    // -------- epilogue: part = sum_rows coefQ[j] * sum_i z1^2 -----------------
    float part = 0.f;
    #pragma unroll
    for (int mt = 0; mt < 2; mt++) {
        int r0 = j0 + m0 + 16 * mt + (lane >> 2);
        float c0 = g_coefQ[r0];
        float c1 = g_coefQ[r0 + 8];
        float s0 = 0.f, s1 = 0.f;
        #pragma unroll
        for (int nt = 0; nt < 8; nt++) {
            s0 = fmaf(acc[mt][nt][0], acc[mt][nt][0], s0);
            s0 = fmaf(acc[mt][nt][1], acc[mt][nt][1], s0);
            s1 = fmaf(acc[mt][nt][2], acc[mt][nt][2], s1);
            s1 = fmaf(acc[mt][nt][3], acc[mt][nt][3], s1);
        }
        part = fmaf(c0, s0, part);
        part = fmaf(c1, s1, part);
    }
    __syncthreads();
    float* red = reinterpret_cast<float*>(gen);
    red[t] = part;
    __syncthreads();
    #pragma unroll
    for (int o = 128; o > 0; o >>= 1) {
        if (t < o) red[t] += red[t + o];
        __syncthreads();
    }
    if (t == 0) atomicAdd(&g_acc, (double)red[0]);
}

// ---------------- finalize ----------------
__global__ void k_final(float* __restrict__ out) { out[0] = (float)g_acc; }

// ---------------- launch ----------------
extern "C" void kernel_launch(void* const* d_in, const int* in_sizes, int n_in,
                              void* d_out, int out_size) {
    const float* x  = (const float*)d_in[0];
    const float* W1 = (const float*)d_in[1];
    const float* b1 = (const float*)d_in[2];
    const float* W2 = (const float*)d_in[3];
    const float* b2 = (const float*)d_in[4];
    const float* W3 = (const float*)d_in[5];
    float* out = (float*)d_out;

    cudaFuncSetAttribute(k_gemm, cudaFuncAttributeMaxDynamicSharedMemorySize, GEMM_SMEM);

    k_init<<<1, 1>>>();
    k_layer1<<<H1, 256>>>(W1, x, b1);
    k_transpose<<<dim3(D / 32, H1 / 32), 256>>>();
    k_layer2<<<H2, 256>>>(W2, b2, W3);
    k_gemm<<<dim3(H2 / 128, D / 128), 256, GEMM_SMEM>>>();
    k_final<<<1, 1>>>(out);
}

// round 5
// speedup vs baseline: 3.9474x; 1.5943x over previous
#include <cuda_runtime.h>
#include <cuda_bf16.h>
#include <math.h>
#include <stdint.h>

#define D   1024
#define H1  4096
#define H2  4096

// ---------------- scratch (static device globals; no allocation) ----------------
__device__ float          g_s[H1];                   // 1 - u0^2
__device__ float          g_u0[H1];
__device__ float          g_g[H1];
__device__ float          g_coefQ[H2];
__device__ double         g_acc;
__device__ __nv_bfloat16  g_W2hi[(size_t)H2 * H1];   // rn(W2)            (32 MB)
__device__ __nv_bfloat16  g_Ahi[(size_t)D * H1];     // (s*W1)^T hi [i][h] (8 MB)
__device__ __nv_bfloat16  g_Alo[(size_t)D * H1];     // (s*W1)^T lo        (8 MB)

// ---------------- portable PTX helpers (sm_80+) ----------------
__device__ __forceinline__ uint32_t smem_u32(const void* p) {
    uint32_t a;
    asm("{ .reg .u64 t; cvta.to.shared.u64 t, %1; cvt.u32.u64 %0, t; }" : "=r"(a) : "l"(p));
    return a;
}
__device__ __forceinline__ void cp16(uint32_t dst, const void* src) {
    asm volatile("cp.async.cg.shared.global [%0], [%1], 16;" :: "r"(dst), "l"(src));
}
#define CP_COMMIT() asm volatile("cp.async.commit_group;" ::: "memory")
template <int N>
__device__ __forceinline__ void cp_wait() {
    asm volatile("cp.async.wait_group %0;" :: "n"(N) : "memory");
}
__device__ __forceinline__ void ldm4(uint32_t addr, uint32_t r[4]) {
    asm volatile("ldmatrix.sync.aligned.m8n8.x4.shared.b16 {%0,%1,%2,%3}, [%4];"
                 : "=r"(r[0]), "=r"(r[1]), "=r"(r[2]), "=r"(r[3]) : "r"(addr));
}
__device__ __forceinline__ void mma16816(float c[4], const uint32_t a[4],
                                         uint32_t b0, uint32_t b1) {
    asm volatile("mma.sync.aligned.m16n8k16.row.col.f32.bf16.bf16.f32 "
                 "{%0,%1,%2,%3}, {%4,%5,%6,%7}, {%8,%9}, {%0,%1,%2,%3};"
                 : "+f"(c[0]), "+f"(c[1]), "+f"(c[2]), "+f"(c[3])
                 : "r"(a[0]), "r"(a[1]), "r"(a[2]), "r"(a[3]), "r"(b0), "r"(b1));
}

// ---------------- init ----------------
__global__ void k_init() { g_acc = 0.0; }

// ---------------- K1: layer-1 row pass (small outputs only) ----------------
__global__ __launch_bounds__(256) void k_layer1(const float* __restrict__ W1,
                                                const float* __restrict__ x,
                                                const float* __restrict__ b1) {
    int h = blockIdx.x;
    int t = threadIdx.x;
    const float4* W4 = reinterpret_cast<const float4*>(W1 + (size_t)h * D);
    const float4* x4 = reinterpret_cast<const float4*>(x);
    float4 w  = W4[t];
    float4 xv = x4[t];
    float dot = w.x * xv.x + w.y * xv.y + w.z * xv.z + w.w * xv.w;
    float r   = w.x * w.x  + w.y * w.y  + w.z * w.z  + w.w * w.w;

    __shared__ float sd[256], sr[256];
    sd[t] = dot; sr[t] = r;
    __syncthreads();
    #pragma unroll
    for (int o = 128; o > 0; o >>= 1) {
        if (t < o) { sd[t] += sd[t + o]; sr[t] += sr[t + o]; }
        __syncthreads();
    }
    if (t == 0) {
        float a0 = sd[0] + b1[h];
        float u0 = tanhf(a0);
        float s  = 1.0f - u0 * u0;
        g_s[h]   = s;
        g_u0[h]  = u0;
        g_g[h]   = -2.0f * u0 * s * sr[0];
    }
}

// ---------------- K_T: transpose W1, scale by s[h], bf16-split ----------------
__global__ __launch_bounds__(256) void k_transpose(const float* __restrict__ W1) {
    __shared__ float tile[32][33];
    __shared__ float ssh[32];
    int i0 = blockIdx.x * 32;
    int h0 = blockIdx.y * 32;
    int tx = threadIdx.x & 31;
    int ty = threadIdx.x >> 5;
    if (ty == 0) ssh[tx] = g_s[h0 + tx];
    #pragma unroll
    for (int r = 0; r < 4; r++)
        tile[ty + r * 8][tx] = W1[(size_t)(h0 + ty + r * 8) * D + i0 + tx];
    __syncthreads();
    #pragma unroll
    for (int r = 0; r < 4; r++) {
        int ii = ty + r * 8;
        float v = tile[tx][ii] * ssh[tx];
        __nv_bfloat16 hi = __float2bfloat16_rn(v);
        float lo = v - __bfloat162float(hi);
        size_t off = (size_t)(i0 + ii) * H1 + h0 + tx;
        g_Ahi[off] = hi;
        g_Alo[off] = __float2bfloat16_rn(lo);
    }
}

// ---------------- K2: layer-2 row pass + W2 -> bf16 (hi only) ----------------
__global__ __launch_bounds__(256) void k_layer2(const float* __restrict__ W2,
                                                const float* __restrict__ b2,
                                                const float* __restrict__ W3) {
    int j = blockIdx.x;
    int t = threadIdx.x;
    const float4* W4 = reinterpret_cast<const float4*>(W2 + (size_t)j * H1);
    const float4* u4 = reinterpret_cast<const float4*>(g_u0);
    const float4* g4 = reinterpret_cast<const float4*>(g_g);
    float z0 = 0.f, sz2 = 0.f;
    #pragma unroll
    for (int k = 0; k < 4; k++) {
        int idx = t + k * 256;
        float4 w  = W4[idx];
        float4 u  = u4[idx];
        float4 gg = g4[idx];
        z0  += w.x * u.x  + w.y * u.y  + w.z * u.z  + w.w * u.w;
        sz2 += w.x * gg.x + w.y * gg.y + w.z * gg.z + w.w * gg.w;
        uint2 hv;
        hv.x = (uint32_t)__bfloat16_as_ushort(__float2bfloat16_rn(w.x))
             | ((uint32_t)__bfloat16_as_ushort(__float2bfloat16_rn(w.y)) << 16);
        hv.y = (uint32_t)__bfloat16_as_ushort(__float2bfloat16_rn(w.z))
             | ((uint32_t)__bfloat16_as_ushort(__float2bfloat16_rn(w.w)) << 16);
        *reinterpret_cast<uint2*>(&g_W2hi[(size_t)j * H1 + (size_t)idx * 4]) = hv;
    }
    __shared__ float sd[256], sr[256];
    sd[t] = z0; sr[t] = sz2;
    __syncthreads();
    #pragma unroll
    for (int o = 128; o > 0; o >>= 1) {
        if (t < o) { sd[t] += sd[t + o]; sr[t] += sr[t + o]; }
        __syncthreads();
    }
    if (t == 0) {
        float v0 = tanhf(sd[0] + b2[j]);
        float tt = 1.0f - v0 * v0;
        float w3 = W3[j];
        atomicAdd(&g_acc, (double)(w3 * tt * sr[0]));
        g_coefQ[j] = -2.0f * w3 * v0 * tt;
    }
}

// ---------------- K3: 2-term mma.sync GEMM + fused square/reduce ----------------
// z1[j,i] = sum_h rn(W2)[j,h] * ((s*W1)^T hi + lo)[i,h];  acc += coefQ[j]*z1^2
// Block 128x128, BK=64, 8 warps (32x64 warp tile), 2-stage cp.async, 1 sync/chunk.
// Stage = Ahi(16K) + Bhi(16K) + Blo(16K). Rows 128B, chunk swizzle c^(row&7).
#define BK        64
#define NCH       (H1 / BK)          // 64
#define TILE_BY   16384
#define STAGE_BY  (3 * TILE_BY)      // 48 KB
#define GEMM_SMEM (1024 + 2 * STAGE_BY)

__global__ __launch_bounds__(256, 2) void k_gemm() {
    extern __shared__ char dyn[];
    uint32_t raw  = smem_u32(dyn);
    uint32_t base = (raw + 1023u) & ~1023u;
    char*    gen  = dyn + (base - raw);

    const int t    = threadIdx.x;
    const int w    = t >> 5;
    const int lane = t & 31;
    const int j0   = blockIdx.x * 128;
    const int i0   = blockIdx.y * 128;

    // -------- cp.async mapping: per tile, thread t handles rows q*32+(t>>3), chunk t&7
    const int rr = t >> 3;                 // base row
    const int cc = t & 7;                  // 16B chunk
    const char* pA = (const char*)(g_W2hi + (size_t)(j0 + rr) * H1 + cc * 8);
    const char* pH = (const char*)(g_Ahi  + (size_t)(i0 + rr) * H1 + cc * 8);
    const char* pL = (const char*)(g_Alo  + (size_t)(i0 + rr) * H1 + cc * 8);
    const uint32_t d0 = base + (uint32_t)(rr * 128 + ((cc ^ (rr & 7)) << 4));
    const size_t rowAdv = (size_t)32 * H1 * 2;   // +32 rows, bytes

    auto load_stage = [&](int s, int kc) {
        const uint32_t sb = (uint32_t)s * STAGE_BY;
        const size_t   gb = (size_t)kc * 128;    // 64 bf16 along k
        #pragma unroll
        for (int q = 0; q < 4; q++)
            cp16(d0 + sb + q * 4096, pA + q * rowAdv + gb);
        #pragma unroll
        for (int q = 0; q < 4; q++)
            cp16(d0 + TILE_BY + sb + q * 4096, pH + q * rowAdv + gb);
        #pragma unroll
        for (int q = 0; q < 4; q++)
            cp16(d0 + 2 * TILE_BY + sb + q * 4096, pL + q * rowAdv + gb);
        CP_COMMIT();
    };

    // -------- warp tiling --------
    const int m0 = (w >> 1) * 32;
    const int n0 = (w & 1) * 64;
    const uint32_t sw   = (uint32_t)(lane & 7);
    const uint32_t rsel = (uint32_t)(lane >> 4);
    uint32_t aRow[2], bRowH[4], bRowL[4];
    #pragma unroll
    for (int mt = 0; mt < 2; mt++)
        aRow[mt] = base + (uint32_t)((m0 + 16 * mt + (lane & 15)) * 128);
    #pragma unroll
    for (int bt = 0; bt < 4; bt++) {
        uint32_t ro = (uint32_t)((n0 + 16 * bt + (lane & 15)) * 128);
        bRowH[bt] = base + TILE_BY     + ro;
        bRowL[bt] = base + 2 * TILE_BY + ro;
    }

    float acc[2][8][4];
    #pragma unroll
    for (int mt = 0; mt < 2; mt++)
        #pragma unroll
        for (int nt = 0; nt < 8; nt++)
            #pragma unroll
            for (int e = 0; e < 4; e++) acc[mt][nt][e] = 0.f;

    load_stage(0, 0);

    #pragma unroll 1
    for (int k = 0; k < NCH; k++) {
        cp_wait<0>();
        __syncthreads();
        if (k + 1 < NCH) load_stage((k + 1) & 1, k + 1);

        const uint32_t sb = (uint32_t)(k & 1) * STAGE_BY;
        #pragma unroll
        for (int ks = 0; ks < 4; ks++) {
            const uint32_t off = (((2 * ks + rsel) ^ sw) << 4) + sb;
            uint32_t ah0[4], ah1[4];
            ldm4(aRow[0] + off, ah0);
            ldm4(aRow[1] + off, ah1);
            #pragma unroll
            for (int bt = 0; bt < 4; bt++) {
                uint32_t bh[4], bl[4];
                ldm4(bRowH[bt] + off, bh);
                ldm4(bRowL[bt] + off, bl);
                #pragma unroll
                for (int p = 0; p < 2; p++) {
                    mma16816(acc[0][bt * 2 + p], ah0, bh[p], bh[2 + p]);
                    mma16816(acc[1][bt * 2 + p], ah1, bh[p], bh[2 + p]);
                    mma16816(acc[0][bt * 2 + p], ah0, bl[p], bl[2 + p]);
                    mma16816(acc[1][bt * 2 + p], ah1, bl[p], bl[2 + p]);
                }
            }
        }
    }

    // -------- epilogue --------
    float part = 0.f;
    #pragma unroll
    for (int mt = 0; mt < 2; mt++) {
        int r0 = j0 + m0 + 16 * mt + (lane >> 2);
        float c0 = g_coefQ[r0];
        float c1 = g_coefQ[r0 + 8];
        float s0 = 0.f, s1 = 0.f;
        #pragma unroll
        for (int nt = 0; nt < 8; nt++) {
            s0 = fmaf(acc[mt][nt][0], acc[mt][nt][0], s0);
            s0 = fmaf(acc[mt][nt][1], acc[mt][nt][1], s0);
            s1 = fmaf(acc[mt][nt][2], acc[mt][nt][2], s1);
            s1 = fmaf(acc[mt][nt][3], acc[mt][nt][3], s1);
        }
        part = fmaf(c0, s0, part);
        part = fmaf(c1, s1, part);
    }
    __syncthreads();
    float* red = reinterpret_cast<float*>(gen);
    red[t] = part;
    __syncthreads();
    #pragma unroll
    for (int o = 128; o > 0; o >>= 1) {
        if (t < o) red[t] += red[t + o];
        __syncthreads();
    }
    if (t == 0) atomicAdd(&g_acc, (double)red[0]);
}

// ---------------- finalize ----------------
__global__ void k_final(float* __restrict__ out) { out[0] = (float)g_acc; }

// ---------------- launch ----------------
extern "C" void kernel_launch(void* const* d_in, const int* in_sizes, int n_in,
                              void* d_out, int out_size) {
    const float* x  = (const float*)d_in[0];
    const float* W1 = (const float*)d_in[1];
    const float* b1 = (const float*)d_in[2];
    const float* W2 = (const float*)d_in[3];
    const float* b2 = (const float*)d_in[4];
    const float* W3 = (const float*)d_in[5];
    float* out = (float*)d_out;

    cudaFuncSetAttribute(k_gemm, cudaFuncAttributeMaxDynamicSharedMemorySize, GEMM_SMEM);

    k_init<<<1, 1>>>();
    k_layer1<<<H1, 256>>>(W1, x, b1);
    k_transpose<<<dim3(D / 32, H1 / 32), 256>>>(W1);
    k_layer2<<<H2, 256>>>(W2, b2, W3);
    k_gemm<<<dim3(H2 / 128, D / 128), 256, GEMM_SMEM>>>();
    k_final<<<1, 1>>>(out);
}

// round 6
// speedup vs baseline: 6.3313x; 1.6039x over previous
#include <cuda_runtime.h>
#include <cuda_bf16.h>
#include <math.h>
#include <stdint.h>

#define D   1024
#define H1  4096
#define H2  4096

// ---------------- scratch (static device globals; no allocation) ----------------
__device__ float          g_s[H1];
__device__ float          g_u0[H1];
__device__ float          g_g[H1];
__device__ float          g_coefQ[H2];
__device__ double         g_acc;
__device__ __nv_bfloat16  g_W2hi[(size_t)H2 * H1];   // rn(W2)       (32 MB)
__device__ __nv_bfloat16  g_Ahi[(size_t)D * H1];     // rn((s*W1)^T) (8 MB)

// ---------------- portable PTX helpers (sm_80+) ----------------
__device__ __forceinline__ uint32_t smem_u32(const void* p) {
    uint32_t a;
    asm("{ .reg .u64 t; cvta.to.shared.u64 t, %1; cvt.u32.u64 %0, t; }" : "=r"(a) : "l"(p));
    return a;
}
__device__ __forceinline__ void cp16(uint32_t dst, const void* src) {
    asm volatile("cp.async.cg.shared.global [%0], [%1], 16;" :: "r"(dst), "l"(src));
}
#define CP_COMMIT() asm volatile("cp.async.commit_group;" ::: "memory")
template <int N>
__device__ __forceinline__ void cp_wait() {
    asm volatile("cp.async.wait_group %0;" :: "n"(N) : "memory");
}
__device__ __forceinline__ void ldm4(uint32_t addr, uint32_t r[4]) {
    asm volatile("ldmatrix.sync.aligned.m8n8.x4.shared.b16 {%0,%1,%2,%3}, [%4];"
                 : "=r"(r[0]), "=r"(r[1]), "=r"(r[2]), "=r"(r[3]) : "r"(addr));
}
__device__ __forceinline__ void mma16816(float c[4], const uint32_t a[4],
                                         uint32_t b0, uint32_t b1) {
    asm volatile("mma.sync.aligned.m16n8k16.row.col.f32.bf16.bf16.f32 "
                 "{%0,%1,%2,%3}, {%4,%5,%6,%7}, {%8,%9}, {%0,%1,%2,%3};"
                 : "+f"(c[0]), "+f"(c[1]), "+f"(c[2]), "+f"(c[3])
                 : "r"(a[0]), "r"(a[1]), "r"(a[2]), "r"(a[3]), "r"(b0), "r"(b1));
}
__device__ __forceinline__ float wred(float v) {
    #pragma unroll
    for (int o = 16; o > 0; o >>= 1)
        v += __shfl_xor_sync(0xFFFFFFFFu, v, o);
    return v;
}

// ---------------- init ----------------
__global__ void k_init() { g_acc = 0.0; }

// ---------------- K1: layer-1, warp per row ----------------
__global__ __launch_bounds__(256) void k_layer1(const float* __restrict__ W1,
                                                const float* __restrict__ x,
                                                const float* __restrict__ b1) {
    int wid  = threadIdx.x >> 5;
    int lane = threadIdx.x & 31;
    int h    = blockIdx.x * 8 + wid;
    const float4* W4 = reinterpret_cast<const float4*>(W1 + (size_t)h * D);
    const float4* x4 = reinterpret_cast<const float4*>(x);
    float dot = 0.f, r = 0.f;
    #pragma unroll
    for (int q = 0; q < 8; q++) {
        float4 w  = W4[lane + q * 32];
        float4 xv = x4[lane + q * 32];
        dot += w.x * xv.x + w.y * xv.y + w.z * xv.z + w.w * xv.w;
        r   += w.x * w.x  + w.y * w.y  + w.z * w.z  + w.w * w.w;
    }
    dot = wred(dot);
    r   = wred(r);
    if (lane == 0) {
        float u0 = tanhf(dot + b1[h]);
        float s  = 1.0f - u0 * u0;
        g_s[h]   = s;
        g_u0[h]  = u0;
        g_g[h]   = -2.0f * u0 * s * r;
    }
}

// ---------------- K_T: transpose W1, scale by s[h], bf16 ----------------
__global__ __launch_bounds__(256) void k_transpose(const float* __restrict__ W1) {
    __shared__ float tile[32][33];
    __shared__ float ssh[32];
    int i0 = blockIdx.x * 32;
    int h0 = blockIdx.y * 32;
    int tx = threadIdx.x & 31;
    int ty = threadIdx.x >> 5;
    if (ty == 0) ssh[tx] = g_s[h0 + tx];
    #pragma unroll
    for (int r = 0; r < 4; r++)
        tile[ty + r * 8][tx] = W1[(size_t)(h0 + ty + r * 8) * D + i0 + tx];
    __syncthreads();
    #pragma unroll
    for (int r = 0; r < 4; r++) {
        int ii = ty + r * 8;
        float v = tile[tx][ii] * ssh[tx];
        g_Ahi[(size_t)(i0 + ii) * H1 + h0 + tx] = __float2bfloat16_rn(v);
    }
}

// ---------------- K2: layer-2 warp-per-row + W2 -> bf16 ----------------
__global__ __launch_bounds__(256) void k_layer2(const float* __restrict__ W2,
                                                const float* __restrict__ b2,
                                                const float* __restrict__ W3) {
    int wid  = threadIdx.x >> 5;
    int lane = threadIdx.x & 31;
    int j    = blockIdx.x * 8 + wid;
    const float4* W4 = reinterpret_cast<const float4*>(W2 + (size_t)j * H1);
    const float4* u4 = reinterpret_cast<const float4*>(g_u0);
    const float4* g4 = reinterpret_cast<const float4*>(g_g);
    uint2* dst = reinterpret_cast<uint2*>(g_W2hi + (size_t)j * H1);
    float z0 = 0.f, sz2 = 0.f;
    #pragma unroll 8
    for (int q = 0; q < 32; q++) {
        int idx = lane + q * 32;
        float4 w  = W4[idx];
        float4 u  = u4[idx];
        float4 gg = g4[idx];
        z0  += w.x * u.x  + w.y * u.y  + w.z * u.z  + w.w * u.w;
        sz2 += w.x * gg.x + w.y * gg.y + w.z * gg.z + w.w * gg.w;
        uint2 hv;
        hv.x = (uint32_t)__bfloat16_as_ushort(__float2bfloat16_rn(w.x))
             | ((uint32_t)__bfloat16_as_ushort(__float2bfloat16_rn(w.y)) << 16);
        hv.y = (uint32_t)__bfloat16_as_ushort(__float2bfloat16_rn(w.z))
             | ((uint32_t)__bfloat16_as_ushort(__float2bfloat16_rn(w.w)) << 16);
        dst[idx] = hv;
    }
    z0  = wred(z0);
    sz2 = wred(sz2);
    if (lane == 0) {
        float v0 = tanhf(z0 + b2[j]);
        float tt = 1.0f - v0 * v0;
        float w3 = W3[j];
        atomicAdd(&g_acc, (double)(w3 * tt * sz2));
        g_coefQ[j] = -2.0f * w3 * v0 * tt;
    }
}

// ---------------- K3: pure-bf16 mma.sync GEMM + fused square/reduce ----------------
// z1[j,i] = sum_h rn(W2)[j,h] * rn((s*W1)^T)[i,h];  acc += coefQ[j]*z1^2
// Block 128x128, BK=64, 8 warps (32x64 warp tile), 3-stage cp.async.
// Stage = A(16K) + B(16K). 128B rows, 16B-chunk swizzle c^(row&7).
#define BK        64
#define NCH       (H1 / BK)          // 64
#define TILE_BY   16384
#define STAGE_BY  (2 * TILE_BY)      // 32 KB
#define GEMM_SMEM (1024 + 3 * STAGE_BY)

__global__ __launch_bounds__(256, 2) void k_gemm() {
    extern __shared__ char dyn[];
    uint32_t raw  = smem_u32(dyn);
    uint32_t base = (raw + 1023u) & ~1023u;
    char*    gen  = dyn + (base - raw);

    const int t    = threadIdx.x;
    const int w    = t >> 5;
    const int lane = t & 31;
    const int j0   = blockIdx.x * 128;
    const int i0   = blockIdx.y * 128;

    // cp.async mapping: rows t>>3 (+32q), 16B chunk t&7
    const int rr = t >> 3;
    const int cc = t & 7;
    const char* pA = (const char*)(g_W2hi + (size_t)(j0 + rr) * H1 + cc * 8);
    const char* pB = (const char*)(g_Ahi  + (size_t)(i0 + rr) * H1 + cc * 8);
    const uint32_t d0 = base + (uint32_t)(rr * 128 + ((cc ^ (rr & 7)) << 4));
    const size_t rowAdv = (size_t)32 * H1 * 2;

    auto load_stage = [&](int s, int kc) {
        const uint32_t sb = (uint32_t)s * STAGE_BY;
        const size_t   gb = (size_t)kc * 128;
        #pragma unroll
        for (int q = 0; q < 4; q++)
            cp16(d0 + sb + q * 4096, pA + q * rowAdv + gb);
        #pragma unroll
        for (int q = 0; q < 4; q++)
            cp16(d0 + TILE_BY + sb + q * 4096, pB + q * rowAdv + gb);
        CP_COMMIT();
    };

    // warp tiling
    const int m0 = (w >> 1) * 32;
    const int n0 = (w & 1) * 64;
    const uint32_t sw   = (uint32_t)(lane & 7);
    const uint32_t rsel = (uint32_t)(lane >> 4);
    uint32_t aRow[2], bRow[4];
    #pragma unroll
    for (int mt = 0; mt < 2; mt++)
        aRow[mt] = base + (uint32_t)((m0 + 16 * mt + (lane & 15)) * 128);
    #pragma unroll
    for (int bt = 0; bt < 4; bt++)
        bRow[bt] = base + TILE_BY + (uint32_t)((n0 + 16 * bt + (lane & 15)) * 128);

    float acc[2][8][4];
    #pragma unroll
    for (int mt = 0; mt < 2; mt++)
        #pragma unroll
        for (int nt = 0; nt < 8; nt++)
            #pragma unroll
            for (int e = 0; e < 4; e++) acc[mt][nt][e] = 0.f;

    load_stage(0, 0);
    load_stage(1, 1);
    load_stage(2, 2);

    int st = 0;
    #pragma unroll 1
    for (int k = 0; k < NCH; k++) {
        cp_wait<2>();
        __syncthreads();
        const uint32_t sb = (uint32_t)st * STAGE_BY;
        #pragma unroll
        for (int ks = 0; ks < 4; ks++) {
            const uint32_t off = (((2 * ks + rsel) ^ sw) << 4) + sb;
            uint32_t ah0[4], ah1[4];
            ldm4(aRow[0] + off, ah0);
            ldm4(aRow[1] + off, ah1);
            #pragma unroll
            for (int bt = 0; bt < 4; bt++) {
                uint32_t bh[4];
                ldm4(bRow[bt] + off, bh);
                #pragma unroll
                for (int p = 0; p < 2; p++) {
                    mma16816(acc[0][bt * 2 + p], ah0, bh[p], bh[2 + p]);
                    mma16816(acc[1][bt * 2 + p], ah1, bh[p], bh[2 + p]);
                }
            }
        }
        __syncthreads();
        if (k + 3 < NCH) load_stage(st, k + 3);
        st = (st == 2) ? 0 : st + 1;
    }

    // epilogue
    float part = 0.f;
    #pragma unroll
    for (int mt = 0; mt < 2; mt++) {
        int r0 = j0 + m0 + 16 * mt + (lane >> 2);
        float c0 = g_coefQ[r0];
        float c1 = g_coefQ[r0 + 8];
        float s0 = 0.f, s1 = 0.f;
        #pragma unroll
        for (int nt = 0; nt < 8; nt++) {
            s0 = fmaf(acc[mt][nt][0], acc[mt][nt][0], s0);
            s0 = fmaf(acc[mt][nt][1], acc[mt][nt][1], s0);
            s1 = fmaf(acc[mt][nt][2], acc[mt][nt][2], s1);
            s1 = fmaf(acc[mt][nt][3], acc[mt][nt][3], s1);
        }
        part = fmaf(c0, s0, part);
        part = fmaf(c1, s1, part);
    }
    __syncthreads();
    float* red = reinterpret_cast<float*>(gen);
    red[t] = part;
    __syncthreads();
    #pragma unroll
    for (int o = 128; o > 0; o >>= 1) {
        if (t < o) red[t] += red[t + o];
        __syncthreads();
    }
    if (t == 0) atomicAdd(&g_acc, (double)red[0]);
}

// ---------------- finalize ----------------
__global__ void k_final(float* __restrict__ out) { out[0] = (float)g_acc; }

// ---------------- launch ----------------
extern "C" void kernel_launch(void* const* d_in, const int* in_sizes, int n_in,
                              void* d_out, int out_size) {
    const float* x  = (const float*)d_in[0];
    const float* W1 = (const float*)d_in[1];
    const float* b1 = (const float*)d_in[2];
    const float* W2 = (const float*)d_in[3];
    const float* b2 = (const float*)d_in[4];
    const float* W3 = (const float*)d_in[5];
    float* out = (float*)d_out;

    cudaFuncSetAttribute(k_gemm, cudaFuncAttributeMaxDynamicSharedMemorySize, GEMM_SMEM);

    k_init<<<1, 1>>>();
    k_layer1<<<H1 / 8, 256>>>(W1, x, b1);
    k_transpose<<<dim3(D / 32, H1 / 32), 256>>>(W1);
    k_layer2<<<H2 / 8, 256>>>(W2, b2, W3);
    k_gemm<<<dim3(H2 / 128, D / 128), 256, GEMM_SMEM>>>();
    k_final<<<1, 1>>>(out);
}

// round 7
// speedup vs baseline: 6.6181x; 1.0453x over previous
#include <cuda_runtime.h>
#include <cuda_bf16.h>
#include <math.h>
#include <stdint.h>

#define D   1024
#define H1  4096
#define H2  4096

// ---------------- scratch (static device globals; no allocation) ----------------
__device__ float          g_s[H1];
__device__ float          g_u0[H1];
__device__ float          g_g[H1];
__device__ float          g_coefQ[H2];
__device__ double         g_acc;
__device__ __nv_bfloat16  g_W2hi[(size_t)H2 * H1];   // rn(W2)       (32 MB)
__device__ __nv_bfloat16  g_Ahi[(size_t)D * H1];     // rn((s*W1)^T) (8 MB)

// ---------------- portable PTX helpers (sm_80+) ----------------
__device__ __forceinline__ uint32_t smem_u32(const void* p) {
    uint32_t a;
    asm("{ .reg .u64 t; cvta.to.shared.u64 t, %1; cvt.u32.u64 %0, t; }" : "=r"(a) : "l"(p));
    return a;
}
__device__ __forceinline__ void cp16(uint32_t dst, const void* src) {
    asm volatile("cp.async.cg.shared.global [%0], [%1], 16;" :: "r"(dst), "l"(src));
}
#define CP_COMMIT() asm volatile("cp.async.commit_group;" ::: "memory")
template <int N>
__device__ __forceinline__ void cp_wait() {
    asm volatile("cp.async.wait_group %0;" :: "n"(N) : "memory");
}
__device__ __forceinline__ void ldm4(uint32_t addr, uint32_t r[4]) {
    asm volatile("ldmatrix.sync.aligned.m8n8.x4.shared.b16 {%0,%1,%2,%3}, [%4];"
                 : "=r"(r[0]), "=r"(r[1]), "=r"(r[2]), "=r"(r[3]) : "r"(addr));
}
__device__ __forceinline__ void mma16816(float c[4], const uint32_t a[4],
                                         uint32_t b0, uint32_t b1) {
    asm volatile("mma.sync.aligned.m16n8k16.row.col.f32.bf16.bf16.f32 "
                 "{%0,%1,%2,%3}, {%4,%5,%6,%7}, {%8,%9}, {%0,%1,%2,%3};"
                 : "+f"(c[0]), "+f"(c[1]), "+f"(c[2]), "+f"(c[3])
                 : "r"(a[0]), "r"(a[1]), "r"(a[2]), "r"(a[3]), "r"(b0), "r"(b1));
}
__device__ __forceinline__ float wred(float v) {
    #pragma unroll
    for (int o = 16; o > 0; o >>= 1)
        v += __shfl_xor_sync(0xFFFFFFFFu, v, o);
    return v;
}

// ---------------- K1: layer-1, warp per row (+ g_acc init) ----------------
__global__ __launch_bounds__(256) void k_layer1(const float* __restrict__ W1,
                                                const float* __restrict__ x,
                                                const float* __restrict__ b1) {
    if (blockIdx.x == 0 && threadIdx.x == 0) g_acc = 0.0;   // ordered before layer2's atomics
    int wid  = threadIdx.x >> 5;
    int lane = threadIdx.x & 31;
    int h    = blockIdx.x * 8 + wid;
    const float4* W4 = reinterpret_cast<const float4*>(W1 + (size_t)h * D);
    const float4* x4 = reinterpret_cast<const float4*>(x);
    float dot = 0.f, r = 0.f;
    #pragma unroll
    for (int q = 0; q < 8; q++) {
        float4 w  = W4[lane + q * 32];
        float4 xv = x4[lane + q * 32];
        dot += w.x * xv.x + w.y * xv.y + w.z * xv.z + w.w * xv.w;
        r   += w.x * w.x  + w.y * w.y  + w.z * w.z  + w.w * w.w;
    }
    dot = wred(dot);
    r   = wred(r);
    if (lane == 0) {
        float u0 = tanhf(dot + b1[h]);
        float s  = 1.0f - u0 * u0;
        g_s[h]   = s;
        g_u0[h]  = u0;
        g_g[h]   = -2.0f * u0 * s * r;
    }
}

// ---------------- K_T: transpose W1, scale by s[h], bf16 ----------------
__global__ __launch_bounds__(256) void k_transpose(const float* __restrict__ W1) {
    __shared__ float tile[32][33];
    __shared__ float ssh[32];
    int i0 = blockIdx.x * 32;
    int h0 = blockIdx.y * 32;
    int tx = threadIdx.x & 31;
    int ty = threadIdx.x >> 5;
    if (ty == 0) ssh[tx] = g_s[h0 + tx];
    #pragma unroll
    for (int r = 0; r < 4; r++)
        tile[ty + r * 8][tx] = W1[(size_t)(h0 + ty + r * 8) * D + i0 + tx];
    __syncthreads();
    #pragma unroll
    for (int r = 0; r < 4; r++) {
        int ii = ty + r * 8;
        float v = tile[tx][ii] * ssh[tx];
        g_Ahi[(size_t)(i0 + ii) * H1 + h0 + tx] = __float2bfloat16_rn(v);
    }
}

// ---------------- K2: layer-2, block per row (R5 shape) + W2 -> bf16 ----------------
__global__ __launch_bounds__(256) void k_layer2(const float* __restrict__ W2,
                                                const float* __restrict__ b2,
                                                const float* __restrict__ W3) {
    int j = blockIdx.x;
    int t = threadIdx.x;
    const float4* W4 = reinterpret_cast<const float4*>(W2 + (size_t)j * H1);
    const float4* u4 = reinterpret_cast<const float4*>(g_u0);
    const float4* g4 = reinterpret_cast<const float4*>(g_g);
    uint2* dst = reinterpret_cast<uint2*>(g_W2hi + (size_t)j * H1);
    float z0 = 0.f, sz2 = 0.f;
    #pragma unroll
    for (int k = 0; k < 4; k++) {
        int idx = t + k * 256;
        float4 w  = W4[idx];
        float4 u  = u4[idx];
        float4 gg = g4[idx];
        z0  += w.x * u.x  + w.y * u.y  + w.z * u.z  + w.w * u.w;
        sz2 += w.x * gg.x + w.y * gg.y + w.z * gg.z + w.w * gg.w;
        uint2 hv;
        hv.x = (uint32_t)__bfloat16_as_ushort(__float2bfloat16_rn(w.x))
             | ((uint32_t)__bfloat16_as_ushort(__float2bfloat16_rn(w.y)) << 16);
        hv.y = (uint32_t)__bfloat16_as_ushort(__float2bfloat16_rn(w.z))
             | ((uint32_t)__bfloat16_as_ushort(__float2bfloat16_rn(w.w)) << 16);
        dst[idx] = hv;
    }
    // two-level reduction: warp shuffle, then 8 partials via shared
    z0  = wred(z0);
    sz2 = wred(sz2);
    __shared__ float pz[8], ps[8];
    int wid = t >> 5, lane = t & 31;
    if (lane == 0) { pz[wid] = z0; ps[wid] = sz2; }
    __syncthreads();
    if (t == 0) {
        float a = 0.f, b = 0.f;
        #pragma unroll
        for (int q = 0; q < 8; q++) { a += pz[q]; b += ps[q]; }
        float v0 = tanhf(a + b2[j]);
        float tt = 1.0f - v0 * v0;
        float w3 = W3[j];
        atomicAdd(&g_acc, (double)(w3 * tt * b));
        g_coefQ[j] = -2.0f * w3 * v0 * tt;
    }
}

// ---------------- K3: pure-bf16 mma.sync GEMM, 1-sync 3-stage pipeline ----------------
// z1[j,i] = sum_h rn(W2)[j,h] * rn((s*W1)^T)[i,h];  acc += coefQ[j]*z1^2
// Block 128x128, BK=64, 8 warps (32x64 warp tile).
// Stage = A(16K)+B(16K). 128B rows, 16B-chunk swizzle c^(row&7).
// Schedule: prologue loads chunks 0,1; iter k: wait<1>, sync, load k+2 into
// stage (k+2)%3 (freed at iter k-1 by this sync), compute stage k%3.
#define BK        64
#define NCH       (H1 / BK)          // 64
#define TILE_BY   16384
#define STAGE_BY  (2 * TILE_BY)      // 32 KB
#define GEMM_SMEM (1024 + 3 * STAGE_BY)

__global__ __launch_bounds__(256, 2) void k_gemm() {
    extern __shared__ char dyn[];
    uint32_t raw  = smem_u32(dyn);
    uint32_t base = (raw + 1023u) & ~1023u;
    char*    gen  = dyn + (base - raw);

    const int t    = threadIdx.x;
    const int w    = t >> 5;
    const int lane = t & 31;
    const int j0   = blockIdx.x * 128;
    const int i0   = blockIdx.y * 128;

    // cp.async mapping: rows t>>3 (+32q), 16B chunk t&7
    const int rr = t >> 3;
    const int cc = t & 7;
    const char* pA = (const char*)(g_W2hi + (size_t)(j0 + rr) * H1 + cc * 8);
    const char* pB = (const char*)(g_Ahi  + (size_t)(i0 + rr) * H1 + cc * 8);
    const uint32_t d0 = base + (uint32_t)(rr * 128 + ((cc ^ (rr & 7)) << 4));
    const size_t rowAdv = (size_t)32 * H1 * 2;

    auto load_stage = [&](int s, int kc) {
        const uint32_t sb = (uint32_t)s * STAGE_BY;
        const size_t   gb = (size_t)kc * 128;
        #pragma unroll
        for (int q = 0; q < 4; q++)
            cp16(d0 + sb + q * 4096, pA + q * rowAdv + gb);
        #pragma unroll
        for (int q = 0; q < 4; q++)
            cp16(d0 + TILE_BY + sb + q * 4096, pB + q * rowAdv + gb);
        CP_COMMIT();
    };

    // warp tiling
    const int m0 = (w >> 1) * 32;
    const int n0 = (w & 1) * 64;
    const uint32_t sw   = (uint32_t)(lane & 7);
    const uint32_t rsel = (uint32_t)(lane >> 4);
    uint32_t aRow[2], bRow[4];
    #pragma unroll
    for (int mt = 0; mt < 2; mt++)
        aRow[mt] = base + (uint32_t)((m0 + 16 * mt + (lane & 15)) * 128);
    #pragma unroll
    for (int bt = 0; bt < 4; bt++)
        bRow[bt] = base + TILE_BY + (uint32_t)((n0 + 16 * bt + (lane & 15)) * 128);

    float acc[2][8][4];
    #pragma unroll
    for (int mt = 0; mt < 2; mt++)
        #pragma unroll
        for (int nt = 0; nt < 8; nt++)
            #pragma unroll
            for (int e = 0; e < 4; e++) acc[mt][nt][e] = 0.f;

    load_stage(0, 0);
    load_stage(1, 1);

    int st = 0;          // stage holding chunk k
    int ld = 2;          // stage to load chunk k+2 into
    #pragma unroll 1
    for (int k = 0; k < NCH; k++) {
        cp_wait<1>();
        __syncthreads();
        if (k + 2 < NCH) load_stage(ld, k + 2);
        const uint32_t sb = (uint32_t)st * STAGE_BY;
        #pragma unroll
        for (int ks = 0; ks < 4; ks++) {
            const uint32_t off = (((2 * ks + rsel) ^ sw) << 4) + sb;
            uint32_t ah0[4], ah1[4];
            ldm4(aRow[0] + off, ah0);
            ldm4(aRow[1] + off, ah1);
            #pragma unroll
            for (int bt = 0; bt < 4; bt++) {
                uint32_t bh[4];
                ldm4(bRow[bt] + off, bh);
                #pragma unroll
                for (int p = 0; p < 2; p++) {
                    mma16816(acc[0][bt * 2 + p], ah0, bh[p], bh[2 + p]);
                    mma16816(acc[1][bt * 2 + p], ah1, bh[p], bh[2 + p]);
                }
            }
        }
        st = (st == 2) ? 0 : st + 1;
        ld = (ld == 2) ? 0 : ld + 1;
    }

    // epilogue
    float part = 0.f;
    #pragma unroll
    for (int mt = 0; mt < 2; mt++) {
        int r0 = j0 + m0 + 16 * mt + (lane >> 2);
        float c0 = g_coefQ[r0];
        float c1 = g_coefQ[r0 + 8];
        float s0 = 0.f, s1 = 0.f;
        #pragma unroll
        for (int nt = 0; nt < 8; nt++) {
            s0 = fmaf(acc[mt][nt][0], acc[mt][nt][0], s0);
            s0 = fmaf(acc[mt][nt][1], acc[mt][nt][1], s0);
            s1 = fmaf(acc[mt][nt][2], acc[mt][nt][2], s1);
            s1 = fmaf(acc[mt][nt][3], acc[mt][nt][3], s1);
        }
        part = fmaf(c0, s0, part);
        part = fmaf(c1, s1, part);
    }
    part += __shfl_xor_sync(0xFFFFFFFFu, part, 16);
    part += __shfl_xor_sync(0xFFFFFFFFu, part, 8);
    part += __shfl_xor_sync(0xFFFFFFFFu, part, 4);
    part += __shfl_xor_sync(0xFFFFFFFFu, part, 2);
    part += __shfl_xor_sync(0xFFFFFFFFu, part, 1);
    __syncthreads();
    float* red = reinterpret_cast<float*>(gen);
    if (lane == 0) red[w] = part;
    __syncthreads();
    if (t == 0) {
        float s = 0.f;
        #pragma unroll
        for (int q = 0; q < 8; q++) s += red[q];
        atomicAdd(&g_acc, (double)s);
    }
}

// ---------------- finalize ----------------
__global__ void k_final(float* __restrict__ out) { out[0] = (float)g_acc; }

// ---------------- launch ----------------
extern "C" void kernel_launch(void* const* d_in, const int* in_sizes, int n_in,
                              void* d_out, int out_size) {
    const float* x  = (const float*)d_in[0];
    const float* W1 = (const float*)d_in[1];
    const float* b1 = (const float*)d_in[2];
    const float* W2 = (const float*)d_in[3];
    const float* b2 = (const float*)d_in[4];
    const float* W3 = (const float*)d_in[5];
    float* out = (float*)d_out;

    cudaFuncSetAttribute(k_gemm, cudaFuncAttributeMaxDynamicSharedMemorySize, GEMM_SMEM);

    k_layer1<<<H1 / 8, 256>>>(W1, x, b1);
    k_transpose<<<dim3(D / 32, H1 / 32), 256>>>(W1);
    k_layer2<<<H2, 256>>>(W2, b2, W3);
    k_gemm<<<dim3(H2 / 128, D / 128), 256, GEMM_SMEM>>>();
    k_final<<<1, 1>>>(out);
}

// round 9
// speedup vs baseline: 6.7067x; 1.0134x over previous
#include <cuda_runtime.h>
#include <cuda_bf16.h>
#include <math.h>
#include <stdint.h>

#define D   1024
#define H1  4096
#define H2  4096

// ---------------- scratch (static device globals; no allocation) ----------------
// Chunk-blocked, pre-swizzled bf16 operand layouts:
//   g_W2t[kc][j][64], g_At[kc][i][64]; within a row, 16B unit c stored at c^(row&7).
__device__ float          g_s[H1];
__device__ float          g_u0[H1];
__device__ float          g_g[H1];
__device__ float          g_coefQ[H2];
__device__ double         g_acc;
__device__ __nv_bfloat16  g_W2t[(size_t)H2 * H1];    // 32 MB
__device__ __nv_bfloat16  g_At[(size_t)D * H1];      // 8 MB

// ---------------- portable PTX helpers (sm_90 baseline, no 'a' features) --------
__device__ __forceinline__ uint32_t smem_u32(const void* p) {
    uint32_t a;
    asm("{ .reg .u64 t; cvta.to.shared.u64 t, %1; cvt.u32.u64 %0, t; }" : "=r"(a) : "l"(p));
    return a;
}
#define MBAR_INIT(mb, c) asm volatile("mbarrier.init.shared.b64 [%0], %1;" :: "r"(mb), "r"(c) : "memory")
#define MBAR_EXPECT(mb, n) asm volatile("mbarrier.arrive.expect_tx.shared.b64 _, [%0], %1;" :: "r"(mb), "r"(n) : "memory")
#define BULK_G2S(dst, src, n, mb) \
    asm volatile("cp.async.bulk.shared::cluster.global.mbarrier::complete_tx::bytes [%0], [%1], %2, [%3];" \
                 :: "r"(dst), "l"(src), "r"(n), "r"(mb) : "memory")
__device__ __forceinline__ void mbar_wait(uint32_t mb, uint32_t parity) {
    uint32_t done;
    asm volatile("{ .reg .pred p; mbarrier.try_wait.parity.acquire.cta.shared::cta.b64 p, [%1], %2; selp.b32 %0, 1, 0, p; }"
                 : "=r"(done) : "r"(mb), "r"(parity) : "memory");
    if (!done) {
        asm volatile("{ .reg .pred P1; WL%=: mbarrier.try_wait.parity.acquire.cta.shared::cta.b64 P1, [%0], %1, 0x989680; @P1 bra.uni WD%=; bra.uni WL%=; WD%=: }"
                     :: "r"(mb), "r"(parity) : "memory");
    }
}
__device__ __forceinline__ void ldm4(uint32_t addr, uint32_t r[4]) {
    asm volatile("ldmatrix.sync.aligned.m8n8.x4.shared.b16 {%0,%1,%2,%3}, [%4];"
                 : "=r"(r[0]), "=r"(r[1]), "=r"(r[2]), "=r"(r[3]) : "r"(addr));
}
__device__ __forceinline__ void mma16816(float c[4], const uint32_t a[4],
                                         uint32_t b0, uint32_t b1) {
    asm volatile("mma.sync.aligned.m16n8k16.row.col.f32.bf16.bf16.f32 "
                 "{%0,%1,%2,%3}, {%4,%5,%6,%7}, {%8,%9}, {%0,%1,%2,%3};"
                 : "+f"(c[0]), "+f"(c[1]), "+f"(c[2]), "+f"(c[3])
                 : "r"(a[0]), "r"(a[1]), "r"(a[2]), "r"(a[3]), "r"(b0), "r"(b1));
}
__device__ __forceinline__ float wred(float v) {
    #pragma unroll
    for (int o = 16; o > 0; o >>= 1)
        v += __shfl_xor_sync(0xFFFFFFFFu, v, o);
    return v;
}

// ---------------- K1: layer-1, warp per row (+ g_acc init) ----------------
__global__ __launch_bounds__(256) void k_layer1(const float* __restrict__ W1,
                                                const float* __restrict__ x,
                                                const float* __restrict__ b1) {
    if (blockIdx.x == 0 && threadIdx.x == 0) g_acc = 0.0;
    int wid  = threadIdx.x >> 5;
    int lane = threadIdx.x & 31;
    int h    = blockIdx.x * 8 + wid;
    const float4* W4 = reinterpret_cast<const float4*>(W1 + (size_t)h * D);
    const float4* x4 = reinterpret_cast<const float4*>(x);
    float dot = 0.f, r = 0.f;
    #pragma unroll
    for (int q = 0; q < 8; q++) {
        float4 w  = W4[lane + q * 32];
        float4 xv = x4[lane + q * 32];
        dot += w.x * xv.x + w.y * xv.y + w.z * xv.z + w.w * xv.w;
        r   += w.x * w.x  + w.y * w.y  + w.z * w.z  + w.w * w.w;
    }
    dot = wred(dot);
    r   = wred(r);
    if (lane == 0) {
        float u0 = tanhf(dot + b1[h]);
        float s  = 1.0f - u0 * u0;
        g_s[h]   = s;
        g_u0[h]  = u0;
        g_g[h]   = -2.0f * u0 * s * r;
    }
}

// ---------------- K_T: transpose W1, scale s[h], bf16, chunk-blocked+swizzled ----
// Block: 32 i x 64 h. Output unit (kc, i, c) at g_At[(kc*D+i)*64 + (c^(i&7))*8].
__global__ __launch_bounds__(256) void k_transpose(const float* __restrict__ W1) {
    __shared__ float tile[64][33];
    __shared__ float ssh[64];
    int i0 = blockIdx.x * 32;
    int h0 = blockIdx.y * 64;
    int t  = threadIdx.x;
    if (t < 64) ssh[t] = g_s[h0 + t];
    {
        int c = t & 31;
        int rbase = (t >> 5) * 8;
        #pragma unroll
        for (int q = 0; q < 8; q++)
            tile[rbase + q][c] = W1[(size_t)(h0 + rbase + q) * D + i0 + c];
    }
    __syncthreads();
    int il = t >> 3;            // 0..31 local i
    int c  = t & 7;             // h-unit within chunk
    int i  = i0 + il;
    unsigned short v[8];
    #pragma unroll
    for (int r = 0; r < 8; r++) {
        int hl = c * 8 + r;
        v[r] = __bfloat16_as_ushort(__float2bfloat16_rn(tile[hl][il] * ssh[hl]));
    }
    uint4 o;
    o.x = (uint32_t)v[0] | ((uint32_t)v[1] << 16);
    o.y = (uint32_t)v[2] | ((uint32_t)v[3] << 16);
    o.z = (uint32_t)v[4] | ((uint32_t)v[5] << 16);
    o.w = (uint32_t)v[6] | ((uint32_t)v[7] << 16);
    size_t off = ((size_t)(h0 >> 6) * D + i) * 64 + ((c ^ (i & 7)) << 3);
    *reinterpret_cast<uint4*>(g_At + off) = o;
}

// ---------------- K2: layer-2, block per row + W2 -> chunk-blocked bf16 ----------
__global__ __launch_bounds__(256) void k_layer2(const float* __restrict__ W2,
                                                const float* __restrict__ b2,
                                                const float* __restrict__ W3) {
    int j = blockIdx.x;
    int t = threadIdx.x;
    const float4* W4 = reinterpret_cast<const float4*>(W2 + (size_t)j * H1);
    const float4* u4 = reinterpret_cast<const float4*>(g_u0);
    const float4* g4 = reinterpret_cast<const float4*>(g_g);
    float z0 = 0.f, sz2 = 0.f;
    #pragma unroll
    for (int q = 0; q < 2; q++) {
        int u = t + q * 256;                 // 8-bf16 unit index (0..511)
        float4 w0 = W4[u * 2];
        float4 w1 = W4[u * 2 + 1];
        float4 ua = u4[u * 2];
        float4 ub = u4[u * 2 + 1];
        float4 ga = g4[u * 2];
        float4 gb = g4[u * 2 + 1];
        z0  += w0.x * ua.x + w0.y * ua.y + w0.z * ua.z + w0.w * ua.w
             + w1.x * ub.x + w1.y * ub.y + w1.z * ub.z + w1.w * ub.w;
        sz2 += w0.x * ga.x + w0.y * ga.y + w0.z * ga.z + w0.w * ga.w
             + w1.x * gb.x + w1.y * gb.y + w1.z * gb.z + w1.w * gb.w;
        uint4 o;
        o.x = (uint32_t)__bfloat16_as_ushort(__float2bfloat16_rn(w0.x))
            | ((uint32_t)__bfloat16_as_ushort(__float2bfloat16_rn(w0.y)) << 16);
        o.y = (uint32_t)__bfloat16_as_ushort(__float2bfloat16_rn(w0.z))
            | ((uint32_t)__bfloat16_as_ushort(__float2bfloat16_rn(w0.w)) << 16);
        o.z = (uint32_t)__bfloat16_as_ushort(__float2bfloat16_rn(w1.x))
            | ((uint32_t)__bfloat16_as_ushort(__float2bfloat16_rn(w1.y)) << 16);
        o.w = (uint32_t)__bfloat16_as_ushort(__float2bfloat16_rn(w1.z))
            | ((uint32_t)__bfloat16_as_ushort(__float2bfloat16_rn(w1.w)) << 16);
        size_t off = ((size_t)(u >> 3) * H2 + j) * 64 + (((u & 7) ^ (j & 7)) << 3);
        *reinterpret_cast<uint4*>(g_W2t + off) = o;
    }
    z0  = wred(z0);
    sz2 = wred(sz2);
    __shared__ float pz[8], ps[8];
    int wid = t >> 5, lane = t & 31;
    if (lane == 0) { pz[wid] = z0; ps[wid] = sz2; }
    __syncthreads();
    if (t == 0) {
        float a = 0.f, b = 0.f;
        #pragma unroll
        for (int q = 0; q < 8; q++) { a += pz[q]; b += ps[q]; }
        float v0 = tanhf(a + b2[j]);
        float tt = 1.0f - v0 * v0;
        float w3 = W3[j];
        atomicAdd(&g_acc, (double)(w3 * tt * b));
        g_coefQ[j] = -2.0f * w3 * v0 * tt;
    }
}

// ---------------- K3: bf16 mma.sync GEMM, bulk-copy 3-stage pipeline ----------------
// z1[j,i] = sum_h rn(W2)[j,h] * rn((s*W1)^T)[i,h];  acc += coefQ[j]*z1^2
// Block 128x128, BK=64, 8 warps (32x64 warp tile).
// Stage = A(16K)+B(16K), filled by TWO cp.async.bulk (contiguous chunk blocks),
// completion via mbarrier complete_tx; stage-free signaled by __syncthreads.
#define BK        64
#define NCH       (H1 / BK)          // 64
#define TILE_BY   16384
#define STAGE_BY  (2 * TILE_BY)      // 32 KB
#define GEMM_SMEM (1024 + 1024 + 3 * STAGE_BY)

__global__ __launch_bounds__(256, 2) void k_gemm() {
    extern __shared__ char dyn[];
    uint32_t raw  = smem_u32(dyn);
    uint32_t base = (raw + 1023u) & ~1023u;
    char*    gen  = dyn + (base - raw);
    const uint32_t stage0 = base + 1024;

    const int t    = threadIdx.x;
    const int w    = t >> 5;
    const int lane = t & 31;
    const int j0   = blockIdx.x * 128;
    const int i0   = blockIdx.y * 128;

    if (t == 0) {
        MBAR_INIT(base + 0, 1);
        MBAR_INIT(base + 8, 1);
        MBAR_INIT(base + 16, 1);
    }
    __syncthreads();

    const char* srcA = (const char*)g_W2t + (size_t)j0 * 128;   // +kc*H2*128
    const char* srcB = (const char*)g_At  + (size_t)i0 * 128;   // +kc*D*128

    auto issue = [&](int s, int kc) {
        uint32_t mb = base + 8u * (uint32_t)s;
        uint32_t db = stage0 + (uint32_t)s * STAGE_BY;
        MBAR_EXPECT(mb, (uint32_t)STAGE_BY);
        BULK_G2S(db,           srcA + (size_t)kc * H2 * 128, (uint32_t)TILE_BY, mb);
        BULK_G2S(db + TILE_BY, srcB + (size_t)kc * D  * 128, (uint32_t)TILE_BY, mb);
    };

    // warp tiling
    const int m0 = (w >> 1) * 32;
    const int n0 = (w & 1) * 64;
    const uint32_t sw   = (uint32_t)(lane & 7);
    const uint32_t rsel = (uint32_t)(lane >> 4);
    uint32_t aRow[2], bRow[4];
    #pragma unroll
    for (int mt = 0; mt < 2; mt++)
        aRow[mt] = stage0 + (uint32_t)((m0 + 16 * mt + (lane & 15)) * 128);
    #pragma unroll
    for (int bt = 0; bt < 4; bt++)
        bRow[bt] = stage0 + TILE_BY + (uint32_t)((n0 + 16 * bt + (lane & 15)) * 128);

    float acc[2][8][4];
    #pragma unroll
    for (int mt = 0; mt < 2; mt++)
        #pragma unroll
        for (int nt = 0; nt < 8; nt++)
            #pragma unroll
            for (int e = 0; e < 4; e++) acc[mt][nt][e] = 0.f;

    if (t == 0) { issue(0, 0); issue(1, 1); }

    int st = 0, ld = 2;
    uint32_t phase[3] = {0u, 0u, 0u};
    #pragma unroll 1
    for (int k = 0; k < NCH; k++) {
        __syncthreads();                       // stage 'ld' fully consumed
        if (t == 0 && k + 2 < NCH) issue(ld, k + 2);
        mbar_wait(base + 8u * (uint32_t)st, phase[st]);
        phase[st] ^= 1u;
        const uint32_t sb = (uint32_t)st * STAGE_BY;
        #pragma unroll
        for (int ks = 0; ks < 4; ks++) {
            const uint32_t off = (((2 * ks + rsel) ^ sw) << 4) + sb;
            uint32_t ah0[4], ah1[4], bh[4][4];
            ldm4(aRow[0] + off, ah0);
            ldm4(aRow[1] + off, ah1);
            ldm4(bRow[0] + off, bh[0]);
            ldm4(bRow[1] + off, bh[1]);
            ldm4(bRow[2] + off, bh[2]);
            ldm4(bRow[3] + off, bh[3]);
            #pragma unroll
            for (int bt = 0; bt < 4; bt++) {
                #pragma unroll
                for (int p = 0; p < 2; p++) {
                    mma16816(acc[0][bt * 2 + p], ah0, bh[bt][p], bh[bt][2 + p]);
                    mma16816(acc[1][bt * 2 + p], ah1, bh[bt][p], bh[bt][2 + p]);
                }
            }
        }
        st = (st == 2) ? 0 : st + 1;
        ld = (ld == 2) ? 0 : ld + 1;
    }

    // epilogue
    float part = 0.f;
    #pragma unroll
    for (int mt = 0; mt < 2; mt++) {
        int r0 = j0 + m0 + 16 * mt + (lane >> 2);
        float c0 = g_coefQ[r0];
        float c1 = g_coefQ[r0 + 8];
        float s0 = 0.f, s1 = 0.f;
        #pragma unroll
        for (int nt = 0; nt < 8; nt++) {
            s0 = fmaf(acc[mt][nt][0], acc[mt][nt][0], s0);
            s0 = fmaf(acc[mt][nt][1], acc[mt][nt][1], s0);
            s1 = fmaf(acc[mt][nt][2], acc[mt][nt][2], s1);
            s1 = fmaf(acc[mt][nt][3], acc[mt][nt][3], s1);
        }
        part = fmaf(c0, s0, part);
        part = fmaf(c1, s1, part);
    }
    part += __shfl_xor_sync(0xFFFFFFFFu, part, 16);
    part += __shfl_xor_sync(0xFFFFFFFFu, part, 8);
    part += __shfl_xor_sync(0xFFFFFFFFu, part, 4);
    part += __shfl_xor_sync(0xFFFFFFFFu, part, 2);
    part += __shfl_xor_sync(0xFFFFFFFFu, part, 1);
    __syncthreads();
    float* red = reinterpret_cast<float*>(gen);
    if (lane == 0) red[w] = part;
    __syncthreads();
    if (t == 0) {
        float s = 0.f;
        #pragma unroll
        for (int q = 0; q < 8; q++) s += red[q];
        atomicAdd(&g_acc, (double)s);
    }
}

// ---------------- finalize ----------------
__global__ void k_final(float* __restrict__ out) { out[0] = (float)g_acc; }

// ---------------- launch ----------------
extern "C" void kernel_launch(void* const* d_in, const int* in_sizes, int n_in,
                              void* d_out, int out_size) {
    const float* x  = (const float*)d_in[0];
    const float* W1 = (const float*)d_in[1];
    const float* b1 = (const float*)d_in[2];
    const float* W2 = (const float*)d_in[3];
    const float* b2 = (const float*)d_in[4];
    const float* W3 = (const float*)d_in[5];
    float* out = (float*)d_out;

    cudaFuncSetAttribute(k_gemm, cudaFuncAttributeMaxDynamicSharedMemorySize, GEMM_SMEM);

    k_layer1<<<H1 / 8, 256>>>(W1, x, b1);
    k_transpose<<<dim3(D / 32, H1 / 64), 256>>>(W1);
    k_layer2<<<H2, 256>>>(W2, b2, W3);
    k_gemm<<<dim3(H2 / 128, D / 128), 256, GEMM_SMEM>>>();
    k_final<<<1, 1>>>(out);
}

// round 10
// speedup vs baseline: 6.7195x; 1.0019x over previous
#include <cuda_runtime.h>
#include <cuda_bf16.h>
#include <math.h>
#include <stdint.h>

#define D   1024
#define H1  4096
#define H2  4096

// ---------------- scratch (static device globals; no allocation) ----------------
// Chunk-blocked, pre-swizzled bf16 operand layouts:
//   g_W2t[kc][j][64], g_At[kc][i][64]; within a row, 16B unit c stored at c^(row&7).
__device__ float          g_s[H1];
__device__ float          g_u0[H1];
__device__ float          g_g[H1];
__device__ float          g_coefQ[H2];
__device__ double         g_acc;
__device__ __nv_bfloat16  g_W2t[(size_t)H2 * H1];    // 32 MB
__device__ __nv_bfloat16  g_At[(size_t)D * H1];      // 8 MB

// ---------------- portable PTX helpers (sm_90 baseline, no 'a' features) --------
__device__ __forceinline__ uint32_t smem_u32(const void* p) {
    uint32_t a;
    asm("{ .reg .u64 t; cvta.to.shared.u64 t, %1; cvt.u32.u64 %0, t; }" : "=r"(a) : "l"(p));
    return a;
}
#define MBAR_INIT(mb, c) asm volatile("mbarrier.init.shared.b64 [%0], %1;" :: "r"(mb), "r"(c) : "memory")
#define MBAR_EXPECT(mb, n) asm volatile("mbarrier.arrive.expect_tx.shared.b64 _, [%0], %1;" :: "r"(mb), "r"(n) : "memory")
#define BULK_G2S(dst, src, n, mb) \
    asm volatile("cp.async.bulk.shared::cluster.global.mbarrier::complete_tx::bytes [%0], [%1], %2, [%3];" \
                 :: "r"(dst), "l"(src), "r"(n), "r"(mb) : "memory")
__device__ __forceinline__ void mbar_wait(uint32_t mb, uint32_t parity) {
    uint32_t done;
    asm volatile("{ .reg .pred p; mbarrier.try_wait.parity.acquire.cta.shared::cta.b64 p, [%1], %2; selp.b32 %0, 1, 0, p; }"
                 : "=r"(done) : "r"(mb), "r"(parity) : "memory");
    if (!done) {
        asm volatile("{ .reg .pred P1; WL%=: mbarrier.try_wait.parity.acquire.cta.shared::cta.b64 P1, [%0], %1, 0x989680; @P1 bra.uni WD%=; bra.uni WL%=; WD%=: }"
                     :: "r"(mb), "r"(parity) : "memory");
    }
}
__device__ __forceinline__ void ldm4(uint32_t addr, uint32_t r[4]) {
    asm volatile("ldmatrix.sync.aligned.m8n8.x4.shared.b16 {%0,%1,%2,%3}, [%4];"
                 : "=r"(r[0]), "=r"(r[1]), "=r"(r[2]), "=r"(r[3]) : "r"(addr));
}
__device__ __forceinline__ void mma16816(float c[4], const uint32_t a[4],
                                         uint32_t b0, uint32_t b1) {
    asm volatile("mma.sync.aligned.m16n8k16.row.col.f32.bf16.bf16.f32 "
                 "{%0,%1,%2,%3}, {%4,%5,%6,%7}, {%8,%9}, {%0,%1,%2,%3};"
                 : "+f"(c[0]), "+f"(c[1]), "+f"(c[2]), "+f"(c[3])
                 : "r"(a[0]), "r"(a[1]), "r"(a[2]), "r"(a[3]), "r"(b0), "r"(b1));
}
__device__ __forceinline__ float wred(float v) {
    #pragma unroll
    for (int o = 16; o > 0; o >>= 1)
        v += __shfl_xor_sync(0xFFFFFFFFu, v, o);
    return v;
}

// ---------------- K1: layer-1, warp per row (+ g_acc init) ----------------
__global__ __launch_bounds__(256) void k_layer1(const float* __restrict__ W1,
                                                const float* __restrict__ x,
                                                const float* __restrict__ b1) {
    if (blockIdx.x == 0 && threadIdx.x == 0) g_acc = 0.0;
    int wid  = threadIdx.x >> 5;
    int lane = threadIdx.x & 31;
    int h    = blockIdx.x * 8 + wid;
    const float4* W4 = reinterpret_cast<const float4*>(W1 + (size_t)h * D);
    const float4* x4 = reinterpret_cast<const float4*>(x);
    float dot = 0.f, r = 0.f;
    #pragma unroll
    for (int q = 0; q < 8; q++) {
        float4 w  = W4[lane + q * 32];
        float4 xv = x4[lane + q * 32];
        dot += w.x * xv.x + w.y * xv.y + w.z * xv.z + w.w * xv.w;
        r   += w.x * w.x  + w.y * w.y  + w.z * w.z  + w.w * w.w;
    }
    dot = wred(dot);
    r   = wred(r);
    if (lane == 0) {
        float u0 = tanhf(dot + b1[h]);
        float s  = 1.0f - u0 * u0;
        g_s[h]   = s;
        g_u0[h]  = u0;
        g_g[h]   = -2.0f * u0 * s * r;
    }
}

// ---------------- K_T: transpose W1, scale s[h], bf16, chunk-blocked+swizzled ----
__global__ __launch_bounds__(256) void k_transpose(const float* __restrict__ W1) {
    __shared__ float tile[64][33];
    __shared__ float ssh[64];
    int i0 = blockIdx.x * 32;
    int h0 = blockIdx.y * 64;
    int t  = threadIdx.x;
    if (t < 64) ssh[t] = g_s[h0 + t];
    {
        int c = t & 31;
        int rbase = (t >> 5) * 8;
        #pragma unroll
        for (int q = 0; q < 8; q++)
            tile[rbase + q][c] = W1[(size_t)(h0 + rbase + q) * D + i0 + c];
    }
    __syncthreads();
    int il = t >> 3;
    int c  = t & 7;
    int i  = i0 + il;
    unsigned short v[8];
    #pragma unroll
    for (int r = 0; r < 8; r++) {
        int hl = c * 8 + r;
        v[r] = __bfloat16_as_ushort(__float2bfloat16_rn(tile[hl][il] * ssh[hl]));
    }
    uint4 o;
    o.x = (uint32_t)v[0] | ((uint32_t)v[1] << 16);
    o.y = (uint32_t)v[2] | ((uint32_t)v[3] << 16);
    o.z = (uint32_t)v[4] | ((uint32_t)v[5] << 16);
    o.w = (uint32_t)v[6] | ((uint32_t)v[7] << 16);
    size_t off = ((size_t)(h0 >> 6) * D + i) * 64 + ((c ^ (i & 7)) << 3);
    *reinterpret_cast<uint4*>(g_At + off) = o;
}

// ---------------- K2: layer-2, block per row + W2 -> chunk-blocked bf16 ----------
__global__ __launch_bounds__(256) void k_layer2(const float* __restrict__ W2,
                                                const float* __restrict__ b2,
                                                const float* __restrict__ W3) {
    int j = blockIdx.x;
    int t = threadIdx.x;
    const float4* W4 = reinterpret_cast<const float4*>(W2 + (size_t)j * H1);
    const float4* u4 = reinterpret_cast<const float4*>(g_u0);
    const float4* g4 = reinterpret_cast<const float4*>(g_g);
    float z0 = 0.f, sz2 = 0.f;
    #pragma unroll
    for (int q = 0; q < 2; q++) {
        int u = t + q * 256;
        float4 w0 = W4[u * 2];
        float4 w1 = W4[u * 2 + 1];
        float4 ua = u4[u * 2];
        float4 ub = u4[u * 2 + 1];
        float4 ga = g4[u * 2];
        float4 gb = g4[u * 2 + 1];
        z0  += w0.x * ua.x + w0.y * ua.y + w0.z * ua.z + w0.w * ua.w
             + w1.x * ub.x + w1.y * ub.y + w1.z * ub.z + w1.w * ub.w;
        sz2 += w0.x * ga.x + w0.y * ga.y + w0.z * ga.z + w0.w * ga.w
             + w1.x * gb.x + w1.y * gb.y + w1.z * gb.z + w1.w * gb.w;
        uint4 o;
        o.x = (uint32_t)__bfloat16_as_ushort(__float2bfloat16_rn(w0.x))
            | ((uint32_t)__bfloat16_as_ushort(__float2bfloat16_rn(w0.y)) << 16);
        o.y = (uint32_t)__bfloat16_as_ushort(__float2bfloat16_rn(w0.z))
            | ((uint32_t)__bfloat16_as_ushort(__float2bfloat16_rn(w0.w)) << 16);
        o.z = (uint32_t)__bfloat16_as_ushort(__float2bfloat16_rn(w1.x))
            | ((uint32_t)__bfloat16_as_ushort(__float2bfloat16_rn(w1.y)) << 16);
        o.w = (uint32_t)__bfloat16_as_ushort(__float2bfloat16_rn(w1.z))
            | ((uint32_t)__bfloat16_as_ushort(__float2bfloat16_rn(w1.w)) << 16);
        size_t off = ((size_t)(u >> 3) * H2 + j) * 64 + (((u & 7) ^ (j & 7)) << 3);
        *reinterpret_cast<uint4*>(g_W2t + off) = o;
    }
    z0  = wred(z0);
    sz2 = wred(sz2);
    __shared__ float pz[8], ps[8];
    int wid = t >> 5, lane = t & 31;
    if (lane == 0) { pz[wid] = z0; ps[wid] = sz2; }
    __syncthreads();
    if (t == 0) {
        float a = 0.f, b = 0.f;
        #pragma unroll
        for (int q = 0; q < 8; q++) { a += pz[q]; b += ps[q]; }
        float v0 = tanhf(a + b2[j]);
        float tt = 1.0f - v0 * v0;
        float w3 = W3[j];
        atomicAdd(&g_acc, (double)(w3 * tt * b));
        g_coefQ[j] = -2.0f * w3 * v0 * tt;
    }
}

// ---------------- K3: bf16 mma.sync GEMM, bulk-copy + fragment pipelining ----------
// Block 128x128, BK=64, 8 warps (32x64 warp tile), 3-stage bulk-copy.
// Inner loop: B-fragment ping-pong + A double-buffer so every LDSM issues
// under a 4-MMA tensor burst (LSU/tensor overlap instead of serial phases).
#define BK        64
#define NCH       (H1 / BK)          // 64
#define TILE_BY   16384
#define STAGE_BY  (2 * TILE_BY)      // 32 KB
#define GEMM_SMEM (1024 + 1024 + 3 * STAGE_BY)

__global__ __launch_bounds__(256, 2) void k_gemm() {
    extern __shared__ char dyn[];
    uint32_t raw  = smem_u32(dyn);
    uint32_t base = (raw + 1023u) & ~1023u;
    char*    gen  = dyn + (base - raw);
    const uint32_t stage0 = base + 1024;

    const int t    = threadIdx.x;
    const int w    = t >> 5;
    const int lane = t & 31;
    const int j0   = blockIdx.x * 128;
    const int i0   = blockIdx.y * 128;

    if (t == 0) {
        MBAR_INIT(base + 0, 1);
        MBAR_INIT(base + 8, 1);
        MBAR_INIT(base + 16, 1);
    }
    __syncthreads();

    const char* srcA = (const char*)g_W2t + (size_t)j0 * 128;
    const char* srcB = (const char*)g_At  + (size_t)i0 * 128;

    auto issue = [&](int s, int kc) {
        uint32_t mb = base + 8u * (uint32_t)s;
        uint32_t db = stage0 + (uint32_t)s * STAGE_BY;
        MBAR_EXPECT(mb, (uint32_t)STAGE_BY);
        BULK_G2S(db,           srcA + (size_t)kc * H2 * 128, (uint32_t)TILE_BY, mb);
        BULK_G2S(db + TILE_BY, srcB + (size_t)kc * D  * 128, (uint32_t)TILE_BY, mb);
    };

    // warp tiling
    const int m0 = (w >> 1) * 32;
    const int n0 = (w & 1) * 64;
    const uint32_t sw   = (uint32_t)(lane & 7);
    const uint32_t rsel = (uint32_t)(lane >> 4);
    uint32_t aRow[2], bRow[4];
    #pragma unroll
    for (int mt = 0; mt < 2; mt++)
        aRow[mt] = stage0 + (uint32_t)((m0 + 16 * mt + (lane & 15)) * 128);
    #pragma unroll
    for (int bt = 0; bt < 4; bt++)
        bRow[bt] = stage0 + TILE_BY + (uint32_t)((n0 + 16 * bt + (lane & 15)) * 128);

    float acc[2][8][4];
    #pragma unroll
    for (int mt = 0; mt < 2; mt++)
        #pragma unroll
        for (int nt = 0; nt < 8; nt++)
            #pragma unroll
            for (int e = 0; e < 4; e++) acc[mt][nt][e] = 0.f;

    if (t == 0) { issue(0, 0); issue(1, 1); }

    int st = 0, ld = 2;
    uint32_t phase[3] = {0u, 0u, 0u};
    #pragma unroll 1
    for (int k = 0; k < NCH; k++) {
        __syncthreads();                       // stage 'ld' fully consumed
        if (t == 0 && k + 2 < NCH) issue(ld, k + 2);
        mbar_wait(base + 8u * (uint32_t)st, phase[st]);
        phase[st] ^= 1u;
        const uint32_t sb = (uint32_t)st * STAGE_BY;
        uint32_t off[4];
        #pragma unroll
        for (int ks = 0; ks < 4; ks++)
            off[ks] = (((2u * ks + rsel) ^ sw) << 4) + sb;

        uint32_t ah[2][2][4];   // [ks&1][mt]
        uint32_t bq[2][4];      // ping-pong B
        ldm4(aRow[0] + off[0], ah[0][0]);
        ldm4(aRow[1] + off[0], ah[0][1]);
        ldm4(bRow[0] + off[0], bq[0]);
        #pragma unroll
        for (int ks = 0; ks < 4; ks++) {
            const int cur = ks & 1, nxt = cur ^ 1;
            #pragma unroll
            for (int bt = 0; bt < 4; bt++) {
                const int pp = bt & 1;
                if (bt == 0 && ks < 3) ldm4(aRow[0] + off[ks + 1], ah[nxt][0]);
                if (bt == 1 && ks < 3) ldm4(aRow[1] + off[ks + 1], ah[nxt][1]);
                if (bt < 3)            ldm4(bRow[bt + 1] + off[ks], bq[pp ^ 1]);
                else if (ks < 3)       ldm4(bRow[0] + off[ks + 1],  bq[pp ^ 1]);
                mma16816(acc[0][bt * 2 + 0], ah[cur][0], bq[pp][0], bq[pp][2]);
                mma16816(acc[0][bt * 2 + 1], ah[cur][0], bq[pp][1], bq[pp][3]);
                mma16816(acc[1][bt * 2 + 0], ah[cur][1], bq[pp][0], bq[pp][2]);
                mma16816(acc[1][bt * 2 + 1], ah[cur][1], bq[pp][1], bq[pp][3]);
            }
        }
        st = (st == 2) ? 0 : st + 1;
        ld = (ld == 2) ? 0 : ld + 1;
    }

    // epilogue
    float part = 0.f;
    #pragma unroll
    for (int mt = 0; mt < 2; mt++) {
        int r0 = j0 + m0 + 16 * mt + (lane >> 2);
        float c0 = g_coefQ[r0];
        float c1 = g_coefQ[r0 + 8];
        float s0 = 0.f, s1 = 0.f;
        #pragma unroll
        for (int nt = 0; nt < 8; nt++) {
            s0 = fmaf(acc[mt][nt][0], acc[mt][nt][0], s0);
            s0 = fmaf(acc[mt][nt][1], acc[mt][nt][1], s0);
            s1 = fmaf(acc[mt][nt][2], acc[mt][nt][2], s1);
            s1 = fmaf(acc[mt][nt][3], acc[mt][nt][3], s1);
        }
        part = fmaf(c0, s0, part);
        part = fmaf(c1, s1, part);
    }
    part += __shfl_xor_sync(0xFFFFFFFFu, part, 16);
    part += __shfl_xor_sync(0xFFFFFFFFu, part, 8);
    part += __shfl_xor_sync(0xFFFFFFFFu, part, 4);
    part += __shfl_xor_sync(0xFFFFFFFFu, part, 2);
    part += __shfl_xor_sync(0xFFFFFFFFu, part, 1);
    __syncthreads();
    float* red = reinterpret_cast<float*>(gen);
    if (lane == 0) red[w] = part;
    __syncthreads();
    if (t == 0) {
        float s = 0.f;
        #pragma unroll
        for (int q = 0; q < 8; q++) s += red[q];
        atomicAdd(&g_acc, (double)s);
    }
}

// ---------------- finalize ----------------
__global__ void k_final(float* __restrict__ out) { out[0] = (float)g_acc; }

// ---------------- launch ----------------
extern "C" void kernel_launch(void* const* d_in, const int* in_sizes, int n_in,
                              void* d_out, int out_size) {
    const float* x  = (const float*)d_in[0];
    const float* W1 = (const float*)d_in[1];
    const float* b1 = (const float*)d_in[2];
    const float* W2 = (const float*)d_in[3];
    const float* b2 = (const float*)d_in[4];
    const float* W3 = (const float*)d_in[5];
    float* out = (float*)d_out;

    cudaFuncSetAttribute(k_gemm, cudaFuncAttributeMaxDynamicSharedMemorySize, GEMM_SMEM);

    k_layer1<<<H1 / 8, 256>>>(W1, x, b1);
    k_transpose<<<dim3(D / 32, H1 / 64), 256>>>(W1);
    k_layer2<<<H2, 256>>>(W2, b2, W3);
    k_gemm<<<dim3(H2 / 128, D / 128), 256, GEMM_SMEM>>>();
    k_final<<<1, 1>>>(out);
}